// round 6
// baseline (speedup 1.0000x reference)
#include <cuda_runtime.h>
#include <math.h>

// Problem constants
#define BATCH 4
#define CCH   192        // channels
#define NPIX  65536      // H*W
#define HEADS 8
#define CH    24         // channels per head (192/8)

// Gram split-K config
#define SPLIT 32
#define KCH   (NPIX / SPLIT)   // 2048

// ---------------- device scratch (static, no allocation) ----------------
__device__ float g_Spart[BATCH * 6 * SPLIT * 4096]; // per (b,tilepair,split) 64x64 partials
__device__ float g_S[BATCH * CCH * CCH];            // Gram X X^T per batch
__device__ float g_attn[BATCH * HEADS * CH * CH];   // softmaxed attention
__device__ float g_M[BATCH * CCH * CCH];            // W_out @ blockdiag(attn)
__device__ float g_P[BATCH * CCH * CCH];            // M @ W_v

// ---------------- tf32 helpers ----------------
__device__ __forceinline__ unsigned f2tf(float f) {
    unsigned u;
    asm("cvt.rna.tf32.f32 %0, %1;" : "=r"(u) : "f"(f));
    return u;
}

__device__ __forceinline__ void mma_tf32(float* d, const unsigned* a,
                                         unsigned b0, unsigned b1) {
    asm volatile(
        "mma.sync.aligned.m16n8k8.row.col.f32.tf32.tf32.f32 "
        "{%0,%1,%2,%3}, {%4,%5,%6,%7}, {%8,%9}, {%0,%1,%2,%3};"
        : "+f"(d[0]), "+f"(d[1]), "+f"(d[2]), "+f"(d[3])
        : "r"(a[0]), "r"(a[1]), "r"(a[2]), "r"(a[3]), "r"(b0), "r"(b1));
}

// tile-pair lookup: 6 upper-triangular 64x64 tiles of the 192x192 Gram
__device__ __forceinline__ void tile_pair(int tp, int& ti, int& tj) {
    ti = (tp < 3) ? 0 : ((tp < 5) ? 1 : 2);
    tj = (tp < 3) ? tp : ((tp < 5) ? tp - 2 : 2);
}

// =====================================================================
// Kernel 1: tf32 partial Gram. grid (6, SPLIT, BATCH), 128 threads.
// Block computes a 64x64 tile of S over a 2048-long K chunk.
// smem strides are 36 (== 4 mod 32) -> all fragment LDS conflict-free.
// =====================================================================
__global__ __launch_bounds__(128) void gram_tc(const float* __restrict__ X) {
    const int tp    = blockIdx.x;
    const int split = blockIdx.y;
    const int b     = blockIdx.z;
    int ti, tj; tile_pair(tp, ti, tj);

    const float* Xb = X + (size_t)b * CCH * NPIX;

    __shared__ unsigned As[64][36];
    __shared__ unsigned Bs[64][36];

    const int t    = threadIdx.x;
    const int lane = t & 31;
    const int wid  = t >> 5;
    const int g    = lane >> 2;   // 0..7
    const int tg   = lane & 3;    // 0..3
    const int wm   = (wid >> 1) * 32;   // warp m base (0/32)
    const int wn   = (wid & 1) * 32;    // warp n base (0/32)

    float acc[2][4][4];
#pragma unroll
    for (int mi = 0; mi < 2; mi++)
#pragma unroll
        for (int nj = 0; nj < 4; nj++)
#pragma unroll
            for (int u = 0; u < 4; u++) acc[mi][nj][u] = 0.f;

    const int kbase = split * KCH;

#pragma unroll 1
    for (int k0 = 0; k0 < KCH; k0 += 32) {
        __syncthreads();
        // load 64x32 A-tile and B-tile (fp32 -> tf32)
#pragma unroll
        for (int i = 0; i < 4; i++) {
            const int idx = t + i * 128;
            const int r = idx >> 3;
            const int c = (idx & 7) << 2;
            float4 a = *(const float4*)(Xb + (size_t)(ti * 64 + r) * NPIX + kbase + k0 + c);
            float4 v = *(const float4*)(Xb + (size_t)(tj * 64 + r) * NPIX + kbase + k0 + c);
            As[r][c + 0] = f2tf(a.x); As[r][c + 1] = f2tf(a.y);
            As[r][c + 2] = f2tf(a.z); As[r][c + 3] = f2tf(a.w);
            Bs[r][c + 0] = f2tf(v.x); Bs[r][c + 1] = f2tf(v.y);
            Bs[r][c + 2] = f2tf(v.z); Bs[r][c + 3] = f2tf(v.w);
        }
        __syncthreads();

#pragma unroll
        for (int kk = 0; kk < 32; kk += 8) {
            unsigned af[2][4], bf[4][2];
#pragma unroll
            for (int mi = 0; mi < 2; mi++) {
                const int m = wm + mi * 16;
                af[mi][0] = As[m + g][kk + tg];
                af[mi][1] = As[m + g + 8][kk + tg];
                af[mi][2] = As[m + g][kk + tg + 4];
                af[mi][3] = As[m + g + 8][kk + tg + 4];
            }
#pragma unroll
            for (int nj = 0; nj < 4; nj++) {
                const int n = wn + nj * 8;
                bf[nj][0] = Bs[n + g][kk + tg];
                bf[nj][1] = Bs[n + g][kk + tg + 4];
            }
#pragma unroll
            for (int mi = 0; mi < 2; mi++)
#pragma unroll
                for (int nj = 0; nj < 4; nj++)
                    mma_tf32(acc[mi][nj], af[mi], bf[nj][0], bf[nj][1]);
        }
    }

    // epilogue: 64x64 partial tile
    float* out = g_Spart + ((size_t)((b * 6 + tp) * SPLIT + split) << 12);
#pragma unroll
    for (int mi = 0; mi < 2; mi++)
#pragma unroll
        for (int nj = 0; nj < 4; nj++) {
            const int m0 = wm + mi * 16 + g;
            const int nc = wn + nj * 8 + 2 * tg;
            float2 lo = make_float2(acc[mi][nj][0], acc[mi][nj][1]);
            float2 hi = make_float2(acc[mi][nj][2], acc[mi][nj][3]);
            *(float2*)&out[m0 * 64 + nc]       = lo;
            *(float2*)&out[(m0 + 8) * 64 + nc] = hi;
        }
}

// =====================================================================
// Kernel 2: deterministic split reduction + symmetric mirror. grid(24).
// =====================================================================
__global__ __launch_bounds__(256) void gram_reduce6() {
    const int blk = blockIdx.x;
    const int b = blk / 6, tp = blk % 6;
    int ti, tj; tile_pair(tp, ti, tj);
    const float* base = g_Spart + ((size_t)(b * 6 + tp) * SPLIT << 12);
    for (int idx = threadIdx.x; idx < 4096; idx += 256) {
        float s = 0.f;
#pragma unroll
        for (int sp = 0; sp < SPLIT; sp++) s += base[(sp << 12) + idx];
        const int i = idx >> 6, j = idx & 63;
        g_S[b * CCH * CCH + (ti * 64 + i) * CCH + (tj * 64 + j)] = s;
        if (ti != tj)
            g_S[b * CCH * CCH + (tj * 64 + j) * CCH + (ti * 64 + i)] = s;
    }
}

// =====================================================================
// Kernel 3: attention. grid (HEADS, BATCH), 192 threads, dynamic smem.
// =====================================================================
#define SD 193
#define ATTN_SMEM ((4 * 24 * SD + 576 + 48) * sizeof(float))

__global__ __launch_bounds__(192) void attn_kernel(const float* __restrict__ wqkv,
                                                   const float* __restrict__ temp) {
    const int h = blockIdx.x, b = blockIdx.y;
    extern __shared__ float sm[];
    float* Wq_s = sm;
    float* Wk_s = Wq_s + 24 * SD;
    float* T1s  = Wk_s + 24 * SD;
    float* T2s  = T1s + 24 * SD;
    float* Gs   = T2s + 24 * SD;
    float* nqv  = Gs + 576;
    float* nkv  = nqv + 24;

    const int tid = threadIdx.x;

    for (int idx = tid; idx < 24 * 192; idx += 192) {
        const int c = idx / 192, a = idx % 192;
        Wq_s[c * SD + a] = wqkv[(h * CH + c) * CCH + a];
        Wk_s[c * SD + a] = wqkv[(CCH + h * CH + c) * CCH + a];
    }
    __syncthreads();

    const int m = tid;
    float aq[CH], ak[CH];
#pragma unroll
    for (int c = 0; c < CH; c++) { aq[c] = 0.f; ak[c] = 0.f; }
    const float* Sb = g_S + b * CCH * CCH;
    for (int a = 0; a < CCH; a++) {
        const float s = Sb[a * CCH + m];
#pragma unroll
        for (int c = 0; c < CH; c++) {
            aq[c] = fmaf(Wq_s[c * SD + a], s, aq[c]);
            ak[c] = fmaf(Wk_s[c * SD + a], s, ak[c]);
        }
    }
#pragma unroll
    for (int c = 0; c < CH; c++) { T1s[c * SD + m] = aq[c]; T2s[c * SD + m] = ak[c]; }
    __syncthreads();

    for (int p = tid; p < 576; p += 192) {
        const int c = p / 24, d = p % 24;
        float gg = 0.f;
        for (int mm = 0; mm < CCH; mm++)
            gg = fmaf(T1s[c * SD + mm], Wk_s[d * SD + mm], gg);
        Gs[p] = gg;
    }
    if (tid < 24) {
        float s = 0.f;
        for (int mm = 0; mm < CCH; mm++)
            s = fmaf(T1s[tid * SD + mm], Wq_s[tid * SD + mm], s);
        nqv[tid] = fmaxf(sqrtf(s), 1e-12f);
    } else if (tid < 48) {
        const int c = tid - 24;
        float s = 0.f;
        for (int mm = 0; mm < CCH; mm++)
            s = fmaf(T2s[c * SD + mm], Wk_s[c * SD + mm], s);
        nkv[c] = fmaxf(sqrtf(s), 1e-12f);
    }
    __syncthreads();

    if (tid < 24) {
        const int c = tid;
        const float tpv = temp[h];
        float l[24];
        float mx = -1e30f;
#pragma unroll
        for (int d = 0; d < 24; d++) {
            l[d] = Gs[c * 24 + d] * tpv / (nqv[c] * nkv[d]);
            mx = fmaxf(mx, l[d]);
        }
        float s = 0.f;
#pragma unroll
        for (int d = 0; d < 24; d++) { l[d] = expf(l[d] - mx); s += l[d]; }
        const float inv = 1.f / s;
        float* arow = g_attn + ((b * HEADS + h) * CH + c) * CH;
#pragma unroll
        for (int d = 0; d < 24; d++) arow[d] = l[d] * inv;
    }
}

// =====================================================================
// Kernel 4: M = W_out @ blockdiag(attn). grid(576), 256 threads.
// =====================================================================
__global__ __launch_bounds__(256) void m_kernel(const float* __restrict__ wout) {
    const int idx = blockIdx.x * 256 + threadIdx.x;
    const int b = idx / (CCH * CCH);
    const int r = idx % (CCH * CCH);
    const int o = r / CCH, j = r % CCH;
    const int h = j / CH, d = j % CH;
    const float* wrow = wout + o * CCH + h * CH;
    const float* acol = g_attn + ((b * HEADS + h) * CH) * CH + d;
    float s = 0.f;
#pragma unroll
    for (int c = 0; c < CH; c++) s = fmaf(wrow[c], acol[c * CH], s);
    g_M[idx] = s;
}

// =====================================================================
// Kernel 5: P = M @ W_v. grid (6,6,BATCH), 256 threads, 32x32 tiles.
// =====================================================================
__global__ __launch_bounds__(256) void p_kernel(const float* __restrict__ wqkv) {
    const int b = blockIdx.z;
    const int i0 = blockIdx.y * 32, j0 = blockIdx.x * 32;
    __shared__ float Ms[32][33], Ws[32][33];
    const int tid = threadIdx.x;
    const int tx = tid % 32, ty = tid / 32;
    float acc[4] = {0.f, 0.f, 0.f, 0.f};
    const float* Mb = g_M + b * CCH * CCH;
    for (int k0 = 0; k0 < CCH; k0 += 32) {
        const int r = tid / 32, kk = tid % 32;
#pragma unroll
        for (int rr = 0; rr < 32; rr += 8) {
            Ms[r + rr][kk] = Mb[(i0 + r + rr) * CCH + k0 + kk];
            Ws[r + rr][kk] = wqkv[(2 * CCH + k0 + r + rr) * CCH + j0 + kk];
        }
        __syncthreads();
#pragma unroll
        for (int k2 = 0; k2 < 32; k2++) {
            const float bv = Ws[k2][tx];
#pragma unroll
            for (int u = 0; u < 4; u++)
                acc[u] = fmaf(Ms[ty + 8 * u][k2], bv, acc[u]);
        }
        __syncthreads();
    }
#pragma unroll
    for (int u = 0; u < 4; u++)
        g_P[b * CCH * CCH + (i0 + ty + 8 * u) * CCH + j0 + tx] = acc[u];
}

// =====================================================================
// Kernel 6: tf32 Y = P @ X. grid (3, 1024, BATCH), 128 threads.
// Computes the OUTPUT TILE TRANSPOSED: Out[n][m] = sum_k X[k][n] * P[m][k]
// -> no smem transposes needed anywhere; strides 68/100 (== 4 mod 32)
//    keep every fragment LDS conflict-free.
// =====================================================================
__global__ __launch_bounds__(128) void y_tc(const float* __restrict__ X,
                                            float* __restrict__ Y) {
    const int b  = blockIdx.z;
    const int i0 = blockIdx.x * 64;   // m (output channel) base
    const int n0 = blockIdx.y * 64;   // pixel base

    __shared__ unsigned Ps[64][100];  // 64 m-rows x 96 k (half of K) + pad
    __shared__ unsigned Xs[32][68];   // 32 k-rows x 64 n + pad

    const float* Pb = g_P + b * CCH * CCH;
    const float* Xb = X + (size_t)b * CCH * NPIX;
    float* Yb       = Y + (size_t)b * CCH * NPIX;

    const int t    = threadIdx.x;
    const int lane = t & 31;
    const int wid  = t >> 5;
    const int g    = lane >> 2;
    const int tg   = lane & 3;
    const int wn_  = (wid >> 1) * 32;  // output-row (n) base of this warp
    const int wm_  = (wid & 1) * 32;   // output-col (m) base of this warp

    float acc[2][4][4];
#pragma unroll
    for (int ni = 0; ni < 2; ni++)
#pragma unroll
        for (int mj = 0; mj < 4; mj++)
#pragma unroll
            for (int u = 0; u < 4; u++) acc[ni][mj][u] = 0.f;

#pragma unroll 1
    for (int kh = 0; kh < CCH; kh += 96) {
#pragma unroll 1
        for (int k0 = 0; k0 < 96; k0 += 32) {
            __syncthreads();
            if (k0 == 0) {
                // load P half: 64 x 96 (fp32 -> tf32)
#pragma unroll
                for (int i = 0; i < 12; i++) {
                    const int idx = t + i * 128;
                    const int r = idx / 24;
                    const int c = (idx % 24) * 4;
                    float4 p = *(const float4*)(Pb + (i0 + r) * CCH + kh + c);
                    Ps[r][c + 0] = f2tf(p.x); Ps[r][c + 1] = f2tf(p.y);
                    Ps[r][c + 2] = f2tf(p.z); Ps[r][c + 3] = f2tf(p.w);
                }
            }
            // load X chunk: 32 k-rows x 64 n
#pragma unroll
            for (int i = 0; i < 4; i++) {
                const int idx = t + i * 128;
                const int r = idx >> 4;
                const int c = (idx & 15) << 2;
                float4 xv = *(const float4*)(Xb + (size_t)(kh + k0 + r) * NPIX + n0 + c);
                Xs[r][c + 0] = f2tf(xv.x); Xs[r][c + 1] = f2tf(xv.y);
                Xs[r][c + 2] = f2tf(xv.z); Xs[r][c + 3] = f2tf(xv.w);
            }
            __syncthreads();

#pragma unroll
            for (int kk = 0; kk < 32; kk += 8) {
                unsigned af[2][4], bf[4][2];
#pragma unroll
                for (int ni = 0; ni < 2; ni++) {
                    const int n = wn_ + ni * 16;
                    af[ni][0] = Xs[kk + tg][n + g];
                    af[ni][1] = Xs[kk + tg][n + g + 8];
                    af[ni][2] = Xs[kk + tg + 4][n + g];
                    af[ni][3] = Xs[kk + tg + 4][n + g + 8];
                }
#pragma unroll
                for (int mj = 0; mj < 4; mj++) {
                    const int mrow = wm_ + mj * 8 + g;
                    bf[mj][0] = Ps[mrow][k0 + kk + tg];
                    bf[mj][1] = Ps[mrow][k0 + kk + tg + 4];
                }
#pragma unroll
                for (int ni = 0; ni < 2; ni++)
#pragma unroll
                    for (int mj = 0; mj < 4; mj++)
                        mma_tf32(acc[ni][mj], af[ni], bf[mj][0], bf[mj][1]);
            }
        }
    }

    // epilogue: D[n'][m'] -> Y[m'][n'] (8-float runs along n = 32B sectors)
#pragma unroll
    for (int ni = 0; ni < 2; ni++)
#pragma unroll
        for (int mj = 0; mj < 4; mj++) {
            const int nrow = wn_ + ni * 16 + g;
            const int mcol = wm_ + mj * 8 + 2 * tg;
            float* y0 = Yb + (size_t)(i0 + mcol) * NPIX + n0;
            float* y1 = Yb + (size_t)(i0 + mcol + 1) * NPIX + n0;
            y0[nrow]     = acc[ni][mj][0];
            y1[nrow]     = acc[ni][mj][1];
            y0[nrow + 8] = acc[ni][mj][2];
            y1[nrow + 8] = acc[ni][mj][3];
        }
}

// =====================================================================
// Launch
// =====================================================================
extern "C" void kernel_launch(void* const* d_in, const int* in_sizes, int n_in,
                              void* d_out, int out_size) {
    const float* x     = (const float*)d_in[0];
    const float* wqkv  = (const float*)d_in[1];
    const float* wout  = (const float*)d_in[2];
    const float* temp  = (const float*)d_in[3];
    float* y           = (float*)d_out;

    (void)in_sizes; (void)n_in; (void)out_size;

    static bool attr_set = false;
    if (!attr_set) {
        cudaFuncSetAttribute(attn_kernel, cudaFuncAttributeMaxDynamicSharedMemorySize,
                             (int)ATTN_SMEM);
        attr_set = true;
    }

    gram_tc<<<dim3(6, SPLIT, BATCH), 128>>>(x);
    gram_reduce6<<<24, 256>>>();
    attn_kernel<<<dim3(HEADS, BATCH), 192, ATTN_SMEM>>>(wqkv, temp);
    m_kernel<<<(BATCH * CCH * CCH) / 256, 256>>>(wout);
    p_kernel<<<dim3(6, 6, BATCH), 256>>>(wqkv);
    y_tc<<<dim3(3, 1024, BATCH), 128>>>(x, y);
}

// round 8
// speedup vs baseline: 1.3678x; 1.3678x over previous
#include <cuda_runtime.h>
#include <cuda_fp16.h>
#include <math.h>

// Problem constants
#define BATCH 4
#define CCH   192
#define NPIX  65536
#define HEADS 8
#define CH    24
#define SPLIT 32
#define KCH   (NPIX / SPLIT)   // 2048

// ---------------- device scratch (static, no allocation) ----------------
__device__ float g_Spart[BATCH * 6 * SPLIT * 4096];
__device__ float g_S[BATCH * CCH * CCH];
__device__ float g_attn[BATCH * HEADS * CH * CH];
__device__ float g_M[BATCH * CCH * CCH];
__device__ float g_P[BATCH * CCH * CCH];

// ---------------- fp16 helpers ----------------
__device__ __forceinline__ unsigned pkh(float a, float b) {
    __half2 h = __floats2half2_rn(a, b);
    return *reinterpret_cast<unsigned*>(&h);
}
__device__ __forceinline__ void mma_h(float* d, const unsigned* a,
                                      unsigned b0, unsigned b1) {
    asm volatile(
        "mma.sync.aligned.m16n8k16.row.col.f32.f16.f16.f32 "
        "{%0,%1,%2,%3}, {%4,%5,%6,%7}, {%8,%9}, {%0,%1,%2,%3};"
        : "+f"(d[0]), "+f"(d[1]), "+f"(d[2]), "+f"(d[3])
        : "r"(a[0]), "r"(a[1]), "r"(a[2]), "r"(a[3]), "r"(b0), "r"(b1));
}
__device__ __forceinline__ void tile_pair(int tp, int& ti, int& tj) {
    ti = (tp < 3) ? 0 : ((tp < 5) ? 1 : 2);
    tj = (tp < 3) ? tp : ((tp < 5) ? tp - 2 : 2);
}

// =====================================================================
// Kernel 1: fp16 partial Gram. grid (6, SPLIT, BATCH), 128 threads.
// 64x64 tile over 2048-pixel chunk, k-step 32, register-staged double buffer.
// smem stride 20 words (== 4 mod 8) -> conflict-free fragment LDS.
// =====================================================================
__global__ __launch_bounds__(128) void gram_h(const float* __restrict__ X) {
    const int tp = blockIdx.x, split = blockIdx.y, b = blockIdx.z;
    int ti, tj; tile_pair(tp, ti, tj);
    const float* Xb = X + (size_t)b * CCH * NPIX;

    __shared__ unsigned As[2][64][20];
    __shared__ unsigned Bs[2][64][20];

    const int t = threadIdx.x, lane = t & 31, wid = t >> 5;
    const int g = lane >> 2, tg = lane & 3;
    const int wm = (wid >> 1) * 32, wn = (wid & 1) * 32;
    const int lr = t >> 3, lc = t & 7;            // load row base / float4 idx

    const float* ag = Xb + (size_t)(ti * 64 + lr) * NPIX + split * KCH + lc * 4;
    const float* bg = Xb + (size_t)(tj * 64 + lr) * NPIX + split * KCH + lc * 4;

    float acc[2][4][4];
#pragma unroll
    for (int mi = 0; mi < 2; mi++)
#pragma unroll
        for (int nj = 0; nj < 4; nj++)
#pragma unroll
            for (int u = 0; u < 4; u++) acc[mi][nj][u] = 0.f;

    // preload chunk 0
    float4 apf[4], bpf[4];
#pragma unroll
    for (int i = 0; i < 4; i++) {
        apf[i] = *(const float4*)(ag + (size_t)(i * 16) * NPIX);
        bpf[i] = *(const float4*)(bg + (size_t)(i * 16) * NPIX);
    }
#pragma unroll
    for (int i = 0; i < 4; i++) {
        *(uint2*)&As[0][lr + i * 16][lc * 2] = make_uint2(pkh(apf[i].x, apf[i].y), pkh(apf[i].z, apf[i].w));
        *(uint2*)&Bs[0][lr + i * 16][lc * 2] = make_uint2(pkh(bpf[i].x, bpf[i].y), pkh(bpf[i].z, bpf[i].w));
    }
    __syncthreads();

    int buf = 0;
    const int NT = KCH / 32;   // 64 chunks
#pragma unroll 1
    for (int kt = 0; kt < NT; kt++) {
        if (kt + 1 < NT) {
#pragma unroll
            for (int i = 0; i < 4; i++) {
                apf[i] = *(const float4*)(ag + (size_t)(i * 16) * NPIX + (kt + 1) * 32);
                bpf[i] = *(const float4*)(bg + (size_t)(i * 16) * NPIX + (kt + 1) * 32);
            }
        }
#pragma unroll
        for (int kk8 = 0; kk8 < 16; kk8 += 8) {
            unsigned af[2][4], bf[4][2];
#pragma unroll
            for (int mi = 0; mi < 2; mi++) {
                const int m = wm + mi * 16;
                af[mi][0] = As[buf][m + g][kk8 + tg];
                af[mi][1] = As[buf][m + g + 8][kk8 + tg];
                af[mi][2] = As[buf][m + g][kk8 + tg + 4];
                af[mi][3] = As[buf][m + g + 8][kk8 + tg + 4];
            }
#pragma unroll
            for (int nj = 0; nj < 4; nj++) {
                const int n = wn + nj * 8;
                bf[nj][0] = Bs[buf][n + g][kk8 + tg];
                bf[nj][1] = Bs[buf][n + g][kk8 + tg + 4];
            }
#pragma unroll
            for (int mi = 0; mi < 2; mi++)
#pragma unroll
                for (int nj = 0; nj < 4; nj++)
                    mma_h(acc[mi][nj], af[mi], bf[nj][0], bf[nj][1]);
        }
        if (kt + 1 < NT) {
            const int nb = buf ^ 1;
#pragma unroll
            for (int i = 0; i < 4; i++) {
                *(uint2*)&As[nb][lr + i * 16][lc * 2] = make_uint2(pkh(apf[i].x, apf[i].y), pkh(apf[i].z, apf[i].w));
                *(uint2*)&Bs[nb][lr + i * 16][lc * 2] = make_uint2(pkh(bpf[i].x, bpf[i].y), pkh(bpf[i].z, bpf[i].w));
            }
            __syncthreads();
            buf = nb;
        }
    }

    float* out = g_Spart + ((size_t)((b * 6 + tp) * SPLIT + split) << 12);
#pragma unroll
    for (int mi = 0; mi < 2; mi++)
#pragma unroll
        for (int nj = 0; nj < 4; nj++) {
            const int m0 = wm + mi * 16 + g;
            const int nc = wn + nj * 8 + 2 * tg;
            *(float2*)&out[m0 * 64 + nc]       = make_float2(acc[mi][nj][0], acc[mi][nj][1]);
            *(float2*)&out[(m0 + 8) * 64 + nc] = make_float2(acc[mi][nj][2], acc[mi][nj][3]);
        }
}

// =====================================================================
// Kernel 2: deterministic split reduction + mirror. grid(24), 256 thr.
// =====================================================================
__global__ __launch_bounds__(256) void gram_reduce6() {
    const int blk = blockIdx.x;
    const int b = blk / 6, tp = blk % 6;
    int ti, tj; tile_pair(tp, ti, tj);
    const float* base = g_Spart + ((size_t)(b * 6 + tp) * SPLIT << 12);
    for (int idx = threadIdx.x; idx < 4096; idx += 256) {
        float s = 0.f;
#pragma unroll
        for (int sp = 0; sp < SPLIT; sp++) s += base[(sp << 12) + idx];
        const int i = idx >> 6, j = idx & 63;
        g_S[b * CCH * CCH + (ti * 64 + i) * CCH + (tj * 64 + j)] = s;
        if (ti != tj)
            g_S[b * CCH * CCH + (tj * 64 + j) * CCH + (ti * 64 + i)] = s;
    }
}

// =====================================================================
// Kernel 3: attention. grid (HEADS, BATCH), 192 threads, dynamic smem.
// =====================================================================
#define SD 193
#define ATTN_SMEM ((4 * 24 * SD + 576 + 48) * sizeof(float))

__global__ __launch_bounds__(192) void attn_kernel(const float* __restrict__ wqkv,
                                                   const float* __restrict__ temp) {
    const int h = blockIdx.x, b = blockIdx.y;
    extern __shared__ float smf[];
    float* Wq_s = smf;
    float* Wk_s = Wq_s + 24 * SD;
    float* T1s  = Wk_s + 24 * SD;
    float* T2s  = T1s + 24 * SD;
    float* Gs   = T2s + 24 * SD;
    float* nqv  = Gs + 576;
    float* nkv  = nqv + 24;
    const int tid = threadIdx.x;

    for (int idx = tid; idx < 24 * 192; idx += 192) {
        const int c = idx / 192, a = idx % 192;
        Wq_s[c * SD + a] = wqkv[(h * CH + c) * CCH + a];
        Wk_s[c * SD + a] = wqkv[(CCH + h * CH + c) * CCH + a];
    }
    __syncthreads();

    const int m = tid;
    float aq[CH], ak[CH];
#pragma unroll
    for (int c = 0; c < CH; c++) { aq[c] = 0.f; ak[c] = 0.f; }
    const float* Sb = g_S + b * CCH * CCH;
    for (int a = 0; a < CCH; a++) {
        const float s = Sb[a * CCH + m];
#pragma unroll
        for (int c = 0; c < CH; c++) {
            aq[c] = fmaf(Wq_s[c * SD + a], s, aq[c]);
            ak[c] = fmaf(Wk_s[c * SD + a], s, ak[c]);
        }
    }
#pragma unroll
    for (int c = 0; c < CH; c++) { T1s[c * SD + m] = aq[c]; T2s[c * SD + m] = ak[c]; }
    __syncthreads();

    for (int p = tid; p < 576; p += 192) {
        const int c = p / 24, d = p % 24;
        float gg = 0.f;
        for (int mm = 0; mm < CCH; mm++)
            gg = fmaf(T1s[c * SD + mm], Wk_s[d * SD + mm], gg);
        Gs[p] = gg;
    }
    if (tid < 24) {
        float s = 0.f;
        for (int mm = 0; mm < CCH; mm++)
            s = fmaf(T1s[tid * SD + mm], Wq_s[tid * SD + mm], s);
        nqv[tid] = fmaxf(sqrtf(s), 1e-12f);
    } else if (tid < 48) {
        const int c = tid - 24;
        float s = 0.f;
        for (int mm = 0; mm < CCH; mm++)
            s = fmaf(T2s[c * SD + mm], Wk_s[c * SD + mm], s);
        nkv[c] = fmaxf(sqrtf(s), 1e-12f);
    }
    __syncthreads();

    if (tid < 24) {
        const int c = tid;
        const float tpv = temp[h];
        float l[24];
        float mx = -1e30f;
#pragma unroll
        for (int d = 0; d < 24; d++) {
            l[d] = Gs[c * 24 + d] * tpv / (nqv[c] * nkv[d]);
            mx = fmaxf(mx, l[d]);
        }
        float s = 0.f;
#pragma unroll
        for (int d = 0; d < 24; d++) { l[d] = expf(l[d] - mx); s += l[d]; }
        const float inv = 1.f / s;
        float* arow = g_attn + ((b * HEADS + h) * CH + c) * CH;
#pragma unroll
        for (int d = 0; d < 24; d++) arow[d] = l[d] * inv;
    }
}

// =====================================================================
// Kernel 4: M = W_out @ blockdiag(attn). grid(576), 256 threads.
// =====================================================================
__global__ __launch_bounds__(256) void m_kernel(const float* __restrict__ wout) {
    const int idx = blockIdx.x * 256 + threadIdx.x;
    const int b = idx / (CCH * CCH);
    const int r = idx % (CCH * CCH);
    const int o = r / CCH, j = r % CCH;
    const int h = j / CH, d = j % CH;
    const float* wrow = wout + o * CCH + h * CH;
    const float* acol = g_attn + ((b * HEADS + h) * CH) * CH + d;
    float s = 0.f;
#pragma unroll
    for (int c = 0; c < CH; c++) s = fmaf(wrow[c], acol[c * CH], s);
    g_M[idx] = s;
}

// =====================================================================
// Kernel 5: P = M @ W_v. grid (6,6,BATCH), 256 threads.
// =====================================================================
__global__ __launch_bounds__(256) void p_kernel(const float* __restrict__ wqkv) {
    const int b = blockIdx.z;
    const int i0 = blockIdx.y * 32, j0 = blockIdx.x * 32;
    __shared__ float Ms[32][33], Ws[32][33];
    const int tid = threadIdx.x;
    const int tx = tid % 32, ty = tid / 32;
    float acc[4] = {0.f, 0.f, 0.f, 0.f};
    const float* Mb = g_M + b * CCH * CCH;
    for (int k0 = 0; k0 < CCH; k0 += 32) {
        const int r0 = tid / 32, kk = tid % 32;
#pragma unroll
        for (int rr = 0; rr < 32; rr += 8) {
            Ms[r0 + rr][kk] = Mb[(i0 + r0 + rr) * CCH + k0 + kk];
            Ws[r0 + rr][kk] = wqkv[(2 * CCH + k0 + r0 + rr) * CCH + j0 + kk];
        }
        __syncthreads();
#pragma unroll
        for (int k2 = 0; k2 < 32; k2++) {
            const float bv = Ws[k2][tx];
#pragma unroll
            for (int u = 0; u < 4; u++)
                acc[u] = fmaf(Ms[ty + 8 * u][k2], bv, acc[u]);
        }
        __syncthreads();
    }
#pragma unroll
    for (int u = 0; u < 4; u++)
        g_P[b * CCH * CCH + (i0 + ty + 8 * u) * CCH + j0 + tx] = acc[u];
}

// =====================================================================
// Kernel 6: fp16 Y = P @ X, output computed transposed (Out[n][m]).
// grid (3, 1024, BATCH), 128 threads. P (64x192) resident in smem;
// X chunks (32k x 64n) double-buffered via registers.
// Strides: Ps 100 (==4 mod 8), Xs 72 (==8 mod 32, blocks of 8) -> conflict-free.
// =====================================================================
__global__ __launch_bounds__(128) void y_h(const float* __restrict__ X,
                                           float* __restrict__ Y) {
    const int b  = blockIdx.z;
    const int i0 = blockIdx.x * 64;   // channel base
    const int n0 = blockIdx.y * 64;   // pixel base

    __shared__ unsigned Ps[64][100];      // 64 m x 96 kpairs (+pad)
    __shared__ unsigned Xs[2][16][72];    // 16 kpairs x 64 n (+pad)

    const float* Pb = g_P + b * CCH * CCH;
    const float* Xb = X + (size_t)b * CCH * NPIX;
    float* Yb       = Y + (size_t)b * CCH * NPIX;

    const int t = threadIdx.x, lane = t & 31, wid = t >> 5;
    const int g = lane >> 2, tg = lane & 3;
    const int wn_ = (wid >> 1) * 32;   // n base
    const int wm_ = (wid & 1) * 32;    // m base
    const int kp = t >> 3, nq = (t & 7) * 8;

    // load P: 64 x 192 fp32 -> half2 (3072 float4s, 24 per thread)
#pragma unroll
    for (int i = 0; i < 24; i++) {
        const int idx = t + i * 128;
        const int r = idx / 48, c4 = idx % 48;
        float4 p = *(const float4*)(Pb + (i0 + r) * CCH + c4 * 4);
        *(uint2*)&Ps[r][c4 * 2] = make_uint2(pkh(p.x, p.y), pkh(p.z, p.w));
    }

    // preload X chunk 0: rows 2kp, 2kp+1, pixels n0+nq..+7
    float4 x0a, x0b, x1a, x1b;
    {
        const float* r0 = Xb + (size_t)(2 * kp) * NPIX + n0 + nq;
        const float* r1 = r0 + NPIX;
        x0a = *(const float4*)r0;       x0b = *(const float4*)(r0 + 4);
        x1a = *(const float4*)r1;       x1b = *(const float4*)(r1 + 4);
    }
    {
        uint4 v0 = make_uint4(pkh(x0a.x, x1a.x), pkh(x0a.y, x1a.y),
                              pkh(x0a.z, x1a.z), pkh(x0a.w, x1a.w));
        uint4 v1 = make_uint4(pkh(x0b.x, x1b.x), pkh(x0b.y, x1b.y),
                              pkh(x0b.z, x1b.z), pkh(x0b.w, x1b.w));
        *(uint4*)&Xs[0][kp][nq]     = v0;
        *(uint4*)&Xs[0][kp][nq + 4] = v1;
    }
    __syncthreads();

    float acc[2][4][4];
#pragma unroll
    for (int ni = 0; ni < 2; ni++)
#pragma unroll
        for (int mj = 0; mj < 4; mj++)
#pragma unroll
            for (int u = 0; u < 4; u++) acc[ni][mj][u] = 0.f;

    int buf = 0;
#pragma unroll 1
    for (int c = 0; c < 6; c++) {
        if (c < 5) {
            const float* r0 = Xb + (size_t)((c + 1) * 32 + 2 * kp) * NPIX + n0 + nq;
            const float* r1 = r0 + NPIX;
            x0a = *(const float4*)r0;   x0b = *(const float4*)(r0 + 4);
            x1a = *(const float4*)r1;   x1b = *(const float4*)(r1 + 4);
        }
#pragma unroll
        for (int k8 = 0; k8 < 16; k8 += 8) {
            unsigned af[2][4], bf[4][2];
#pragma unroll
            for (int ni = 0; ni < 2; ni++) {
                const int n = wn_ + ni * 16;
                af[ni][0] = Xs[buf][k8 + tg][n + g];
                af[ni][1] = Xs[buf][k8 + tg][n + g + 8];
                af[ni][2] = Xs[buf][k8 + tg + 4][n + g];
                af[ni][3] = Xs[buf][k8 + tg + 4][n + g + 8];
            }
#pragma unroll
            for (int mj = 0; mj < 4; mj++) {
                const int mrow = wm_ + mj * 8 + g;
                bf[mj][0] = Ps[mrow][c * 16 + k8 + tg];
                bf[mj][1] = Ps[mrow][c * 16 + k8 + tg + 4];
            }
#pragma unroll
            for (int ni = 0; ni < 2; ni++)
#pragma unroll
                for (int mj = 0; mj < 4; mj++)
                    mma_h(acc[ni][mj], af[ni], bf[mj][0], bf[mj][1]);
        }
        if (c < 5) {
            const int nb = buf ^ 1;
            uint4 v0 = make_uint4(pkh(x0a.x, x1a.x), pkh(x0a.y, x1a.y),
                                  pkh(x0a.z, x1a.z), pkh(x0a.w, x1a.w));
            uint4 v1 = make_uint4(pkh(x0b.x, x1b.x), pkh(x0b.y, x1b.y),
                                  pkh(x0b.z, x1b.z), pkh(x0b.w, x1b.w));
            *(uint4*)&Xs[nb][kp][nq]     = v0;
            *(uint4*)&Xs[nb][kp][nq + 4] = v1;
            __syncthreads();
            buf = nb;
        }
    }

    // epilogue: D[n'][m'] -> Y[m'][n']
#pragma unroll
    for (int ni = 0; ni < 2; ni++)
#pragma unroll
        for (int mj = 0; mj < 4; mj++) {
            const int nrow = wn_ + ni * 16 + g;
            const int mcol = wm_ + mj * 8 + 2 * tg;
            float* y0 = Yb + (size_t)(i0 + mcol) * NPIX + n0;
            float* y1 = Yb + (size_t)(i0 + mcol + 1) * NPIX + n0;
            y0[nrow]     = acc[ni][mj][0];
            y1[nrow]     = acc[ni][mj][1];
            y0[nrow + 8] = acc[ni][mj][2];
            y1[nrow + 8] = acc[ni][mj][3];
        }
}

// =====================================================================
// Launch
// =====================================================================
extern "C" void kernel_launch(void* const* d_in, const int* in_sizes, int n_in,
                              void* d_out, int out_size) {
    const float* x    = (const float*)d_in[0];
    const float* wqkv = (const float*)d_in[1];
    const float* wout = (const float*)d_in[2];
    const float* temp = (const float*)d_in[3];
    float* y          = (float*)d_out;
    (void)in_sizes; (void)n_in; (void)out_size;

    static bool attr_set = false;
    if (!attr_set) {
        cudaFuncSetAttribute(attn_kernel, cudaFuncAttributeMaxDynamicSharedMemorySize,
                             (int)ATTN_SMEM);
        attr_set = true;
    }

    gram_h<<<dim3(6, SPLIT, BATCH), 128>>>(x);
    gram_reduce6<<<24, 256>>>();
    attn_kernel<<<dim3(HEADS, BATCH), 192, ATTN_SMEM>>>(wqkv, temp);
    m_kernel<<<576, 256>>>(wout);
    p_kernel<<<dim3(6, 6, BATCH), 256>>>(wqkv);
    y_h<<<dim3(3, 1024, BATCH), 128>>>(x, y);
}

// round 9
// speedup vs baseline: 1.6197x; 1.1842x over previous
#include <cuda_runtime.h>
#include <cuda_fp16.h>
#include <math.h>
#include <stdint.h>

// Problem constants
#define BATCH 4
#define CCH   192
#define NPIX  65536
#define HEADS 8
#define CH    24
#define SPLIT 32
#define KCH   (NPIX / SPLIT)   // 2048

// ---------------- device scratch (static, no allocation) ----------------
__device__ float g_Spart[BATCH * 6 * SPLIT * 4096];
__device__ float g_S[BATCH * CCH * CCH];
__device__ float g_attn[BATCH * HEADS * CH * CH];
__device__ float g_M[BATCH * CCH * CCH];
__device__ float g_P[BATCH * CCH * CCH];
__device__ __align__(16) __half g_Xh[(size_t)BATCH * CCH * NPIX];

// ---------------- helpers ----------------
__device__ __forceinline__ unsigned pkh(float a, float b) {
    __half2 h = __floats2half2_rn(a, b);
    return *reinterpret_cast<unsigned*>(&h);
}
__device__ __forceinline__ uint32_t s2u(const void* p) {
    uint32_t a;
    asm("{.reg .u64 t; cvta.to.shared.u64 t, %1; cvt.u32.u64 %0, t;}" : "=r"(a) : "l"(p));
    return a;
}
__device__ __forceinline__ void mma_h(float* d, const unsigned* a,
                                      unsigned b0, unsigned b1) {
    asm volatile(
        "mma.sync.aligned.m16n8k16.row.col.f32.f16.f16.f32 "
        "{%0,%1,%2,%3}, {%4,%5,%6,%7}, {%8,%9}, {%0,%1,%2,%3};"
        : "+f"(d[0]), "+f"(d[1]), "+f"(d[2]), "+f"(d[3])
        : "r"(a[0]), "r"(a[1]), "r"(a[2]), "r"(a[3]), "r"(b0), "r"(b1));
}
__device__ __forceinline__ void ldm_x4(unsigned* r, uint32_t a) {
    asm volatile("ldmatrix.sync.aligned.m8n8.x4.shared.b16 {%0,%1,%2,%3}, [%4];"
                 : "=r"(r[0]), "=r"(r[1]), "=r"(r[2]), "=r"(r[3]) : "r"(a));
}
__device__ __forceinline__ void ldm_x4_t(unsigned* r, uint32_t a) {
    asm volatile("ldmatrix.sync.aligned.m8n8.x4.trans.shared.b16 {%0,%1,%2,%3}, [%4];"
                 : "=r"(r[0]), "=r"(r[1]), "=r"(r[2]), "=r"(r[3]) : "r"(a));
}
#define CPA16(dst, src) asm volatile("cp.async.cg.shared.global [%0], [%1], 16;" :: "r"(dst), "l"(src))
#define CPCOMMIT()      asm volatile("cp.async.commit_group;")
#define CPWAIT(n)       asm volatile("cp.async.wait_group %0;" :: "n"(n))

__device__ __forceinline__ void tile_pair(int tp, int& ti, int& tj) {
    ti = (tp < 3) ? 0 : ((tp < 5) ? 1 : 2);
    tj = (tp < 3) ? tp : ((tp < 5) ? tp - 2 : 2);
}

// =====================================================================
// Kernel 0: prep X fp32 -> fp16, same layout. grid (24576), 256 thr.
// =====================================================================
__global__ __launch_bounds__(256) void prep_h(const float* __restrict__ X) {
    const size_t g = ((size_t)blockIdx.x * 256 + threadIdx.x) * 8;
    float4 a = *(const float4*)(X + g);
    float4 b = *(const float4*)(X + g + 4);
    uint4 o = make_uint4(pkh(a.x, a.y), pkh(a.z, a.w), pkh(b.x, b.y), pkh(b.z, b.w));
    *(uint4*)(g_Xh + g) = o;
}

// =====================================================================
// Kernel 1: fp16 partial Gram via cp.async + ldmatrix.
// grid (6, SPLIT, BATCH), 128 threads. 64x64 tile, k-step 64.
// Pitch 72 halves (=9x16B, odd) -> conflict-free ldmatrix.
// =====================================================================
__global__ __launch_bounds__(128) void gram_h2() {
    const int tp = blockIdx.x, split = blockIdx.y, b = blockIdx.z;
    int ti, tj; tile_pair(tp, ti, tj);

    __shared__ __align__(16) __half As[2][64][72];
    __shared__ __align__(16) __half Bs[2][64][72];
    const uint32_t sbA = s2u(As), sbB = s2u(Bs);

    const int t = threadIdx.x, lane = t & 31, wid = t >> 5;
    const int g = lane >> 2, tg = lane & 3;
    const int lr = lane & 15, lu = lane >> 4;
    const int wm = (wid >> 1) * 32, wn = (wid & 1) * 32;
    const int ldr = t >> 1, ldu = (t & 1) * 4;    // cp.async: row, first unit

    const __half* srcA = g_Xh + ((size_t)(b * CCH + ti * 64 + ldr)) * NPIX + split * KCH + ldu * 8;
    const __half* srcB = g_Xh + ((size_t)(b * CCH + tj * 64 + ldr)) * NPIX + split * KCH + ldu * 8;
    const uint32_t dA = sbA + ldr * 144 + ldu * 16;
    const uint32_t dB = sbB + ldr * 144 + ldu * 16;

    float acc[2][4][4];
#pragma unroll
    for (int mi = 0; mi < 2; mi++)
#pragma unroll
        for (int nj = 0; nj < 4; nj++)
#pragma unroll
            for (int u = 0; u < 4; u++) acc[mi][nj][u] = 0.f;

    // prologue: stage 0
#pragma unroll
    for (int j = 0; j < 4; j++) {
        CPA16(dA + j * 16, srcA + j * 8);
        CPA16(dB + j * 16, srcB + j * 8);
    }
    CPCOMMIT();

    int buf = 0;
    const int NT = KCH / 64;   // 32
#pragma unroll 1
    for (int kt = 0; kt < NT; kt++) {
        if (kt + 1 < NT) {
            const uint32_t bo = (buf ^ 1) * 9216;
#pragma unroll
            for (int j = 0; j < 4; j++) {
                CPA16(dA + bo + j * 16, srcA + (kt + 1) * 64 + j * 8);
                CPA16(dB + bo + j * 16, srcB + (kt + 1) * 64 + j * 8);
            }
            CPCOMMIT();
            CPWAIT(1);
        } else {
            CPWAIT(0);
        }
        __syncthreads();

        const uint32_t bo = buf * 9216;
#pragma unroll
        for (int kk = 0; kk < 64; kk += 16) {
            const uint32_t col = ((kk >> 3) + lu) * 16;
            unsigned af[2][4], bf[4][2], tmp[4];
#pragma unroll
            for (int mi = 0; mi < 2; mi++)
                ldm_x4(af[mi], sbA + bo + (wm + mi * 16 + lr) * 144 + col);
#pragma unroll
            for (int nj2 = 0; nj2 < 2; nj2++) {
                ldm_x4(tmp, sbB + bo + (wn + nj2 * 16 + lr) * 144 + col);
                bf[nj2 * 2][0] = tmp[0]; bf[nj2 * 2][1] = tmp[2];
                bf[nj2 * 2 + 1][0] = tmp[1]; bf[nj2 * 2 + 1][1] = tmp[3];
            }
#pragma unroll
            for (int mi = 0; mi < 2; mi++)
#pragma unroll
                for (int nj = 0; nj < 4; nj++)
                    mma_h(acc[mi][nj], af[mi], bf[nj][0], bf[nj][1]);
        }
        __syncthreads();
        buf ^= 1;
    }

    float* out = g_Spart + ((size_t)((b * 6 + tp) * SPLIT + split) << 12);
#pragma unroll
    for (int mi = 0; mi < 2; mi++)
#pragma unroll
        for (int nj = 0; nj < 4; nj++) {
            const int m0 = wm + mi * 16 + g;
            const int nc = wn + nj * 8 + 2 * tg;
            *(float2*)&out[m0 * 64 + nc]       = make_float2(acc[mi][nj][0], acc[mi][nj][1]);
            *(float2*)&out[(m0 + 8) * 64 + nc] = make_float2(acc[mi][nj][2], acc[mi][nj][3]);
        }
}

// =====================================================================
// Kernel 2: split reduction + mirror. grid(96), 256 thr.
// =====================================================================
__global__ __launch_bounds__(256) void gram_reduce6() {
    const int q = blockIdx.x & 3, blk = blockIdx.x >> 2;
    const int b = blk / 6, tp = blk % 6;
    int ti, tj; tile_pair(tp, ti, tj);
    const float* base = g_Spart + ((size_t)(b * 6 + tp) * SPLIT << 12);
    for (int idx = q * 1024 + threadIdx.x; idx < (q + 1) * 1024; idx += 256) {
        float s = 0.f;
#pragma unroll
        for (int sp = 0; sp < SPLIT; sp++) s += base[(sp << 12) + idx];
        const int i = idx >> 6, j = idx & 63;
        g_S[b * CCH * CCH + (ti * 64 + i) * CCH + (tj * 64 + j)] = s;
        if (ti != tj)
            g_S[b * CCH * CCH + (tj * 64 + j) * CCH + (ti * 64 + i)] = s;
    }
}

// =====================================================================
// Kernel 3: attention. grid (HEADS, BATCH), 192 threads, dynamic smem.
// =====================================================================
#define SD 193
#define ATTN_SMEM ((4 * 24 * SD + 576 + 48) * sizeof(float))

__global__ __launch_bounds__(192) void attn_kernel(const float* __restrict__ wqkv,
                                                   const float* __restrict__ temp) {
    const int h = blockIdx.x, b = blockIdx.y;
    extern __shared__ float smf[];
    float* Wq_s = smf;
    float* Wk_s = Wq_s + 24 * SD;
    float* T1s  = Wk_s + 24 * SD;
    float* T2s  = T1s + 24 * SD;
    float* Gs   = T2s + 24 * SD;
    float* nqv  = Gs + 576;
    float* nkv  = nqv + 24;
    const int tid = threadIdx.x;

    for (int idx = tid; idx < 24 * 192; idx += 192) {
        const int c = idx / 192, a = idx % 192;
        Wq_s[c * SD + a] = wqkv[(h * CH + c) * CCH + a];
        Wk_s[c * SD + a] = wqkv[(CCH + h * CH + c) * CCH + a];
    }
    __syncthreads();

    const int m = tid;
    float aq[CH], ak[CH];
#pragma unroll
    for (int c = 0; c < CH; c++) { aq[c] = 0.f; ak[c] = 0.f; }
    const float* Sb = g_S + b * CCH * CCH;
    for (int a = 0; a < CCH; a++) {
        const float s = Sb[a * CCH + m];
#pragma unroll
        for (int c = 0; c < CH; c++) {
            aq[c] = fmaf(Wq_s[c * SD + a], s, aq[c]);
            ak[c] = fmaf(Wk_s[c * SD + a], s, ak[c]);
        }
    }
#pragma unroll
    for (int c = 0; c < CH; c++) { T1s[c * SD + m] = aq[c]; T2s[c * SD + m] = ak[c]; }
    __syncthreads();

    for (int p = tid; p < 576; p += 192) {
        const int c = p / 24, d = p % 24;
        float gg = 0.f;
        for (int mm = 0; mm < CCH; mm++)
            gg = fmaf(T1s[c * SD + mm], Wk_s[d * SD + mm], gg);
        Gs[p] = gg;
    }
    if (tid < 24) {
        float s = 0.f;
        for (int mm = 0; mm < CCH; mm++)
            s = fmaf(T1s[tid * SD + mm], Wq_s[tid * SD + mm], s);
        nqv[tid] = fmaxf(sqrtf(s), 1e-12f);
    } else if (tid < 48) {
        const int c = tid - 24;
        float s = 0.f;
        for (int mm = 0; mm < CCH; mm++)
            s = fmaf(T2s[c * SD + mm], Wk_s[c * SD + mm], s);
        nkv[c] = fmaxf(sqrtf(s), 1e-12f);
    }
    __syncthreads();

    if (tid < 24) {
        const int c = tid;
        const float tpv = temp[h];
        float l[24];
        float mx = -1e30f;
#pragma unroll
        for (int d = 0; d < 24; d++) {
            l[d] = Gs[c * 24 + d] * tpv / (nqv[c] * nkv[d]);
            mx = fmaxf(mx, l[d]);
        }
        float s = 0.f;
#pragma unroll
        for (int d = 0; d < 24; d++) { l[d] = expf(l[d] - mx); s += l[d]; }
        const float inv = 1.f / s;
        float* arow = g_attn + ((b * HEADS + h) * CH + c) * CH;
#pragma unroll
        for (int d = 0; d < 24; d++) arow[d] = l[d] * inv;
    }
}

// =====================================================================
// Kernel 4: M = W_out @ blockdiag(attn). grid(576), 256 threads.
// =====================================================================
__global__ __launch_bounds__(256) void m_kernel(const float* __restrict__ wout) {
    const int idx = blockIdx.x * 256 + threadIdx.x;
    const int b = idx / (CCH * CCH);
    const int r = idx % (CCH * CCH);
    const int o = r / CCH, j = r % CCH;
    const int h = j / CH, d = j % CH;
    const float* wrow = wout + o * CCH + h * CH;
    const float* acol = g_attn + ((b * HEADS + h) * CH) * CH + d;
    float s = 0.f;
#pragma unroll
    for (int c = 0; c < CH; c++) s = fmaf(wrow[c], acol[c * CH], s);
    g_M[idx] = s;
}

// =====================================================================
// Kernel 5: P = M @ W_v. grid (6,6,BATCH), 256 threads.
// =====================================================================
__global__ __launch_bounds__(256) void p_kernel(const float* __restrict__ wqkv) {
    const int b = blockIdx.z;
    const int i0 = blockIdx.y * 32, j0 = blockIdx.x * 32;
    __shared__ float Ms[32][33], Ws[32][33];
    const int tid = threadIdx.x;
    const int tx = tid % 32, ty = tid / 32;
    float acc[4] = {0.f, 0.f, 0.f, 0.f};
    const float* Mb = g_M + b * CCH * CCH;
    for (int k0 = 0; k0 < CCH; k0 += 32) {
        const int r0 = tid / 32, kk = tid % 32;
#pragma unroll
        for (int rr = 0; rr < 32; rr += 8) {
            Ms[r0 + rr][kk] = Mb[(i0 + r0 + rr) * CCH + k0 + kk];
            Ws[r0 + rr][kk] = wqkv[(2 * CCH + k0 + r0 + rr) * CCH + j0 + kk];
        }
        __syncthreads();
#pragma unroll
        for (int k2 = 0; k2 < 32; k2++) {
            const float bv = Ws[k2][tx];
#pragma unroll
            for (int u = 0; u < 4; u++)
                acc[u] = fmaf(Ms[ty + 8 * u][k2], bv, acc[u]);
        }
        __syncthreads();
    }
#pragma unroll
    for (int u = 0; u < 4; u++)
        g_P[b * CCH * CCH + (i0 + ty + 8 * u) * CCH + j0 + tx] = acc[u];
}

// =====================================================================
// Kernel 6: Y = P @ X via cp.async + ldmatrix. grid (3, 512, BATCH), 256 thr.
// Block tile m64 x n128, warp 32x32 (2x4 warps). P resident (pitch 200),
// X chunks 32x128 double-buffered (pitch 136). D[c][pix] direct.
// =====================================================================
__global__ __launch_bounds__(256) void y_h2(float* __restrict__ Y) {
    const int b  = blockIdx.z;
    const int i0 = blockIdx.x * 64;    // channel base
    const int n0 = blockIdx.y * 128;   // pixel base

    __shared__ __align__(16) __half Ps[64][200];
    __shared__ __align__(16) __half Xs[2][32][136];
    const uint32_t sbP = s2u(Ps), sbX = s2u(Xs);

    const int t = threadIdx.x, lane = t & 31, wid = t >> 5;
    const int g = lane >> 2, tg = lane & 3;
    const int lr = lane & 15, lu = lane >> 4;
    const int lb7 = lane & 7, lb8 = (lane >> 3) & 1, lb16 = lane >> 4;
    const int wm = (wid & 1) * 32, wn = (wid >> 1) * 32;

    const float* Pb = g_P + b * CCH * CCH;
    const __half* Xb = g_Xh + (size_t)b * CCH * NPIX;

    // load P (fp32 -> fp16) into smem
#pragma unroll
    for (int i = 0; i < 12; i++) {
        const int idx = t + i * 256;
        const int r = idx / 48, c4 = idx % 48;
        float4 p = *(const float4*)(Pb + (i0 + r) * CCH + c4 * 4);
        *(uint2*)&Ps[r][c4 * 4] = make_uint2(pkh(p.x, p.y), pkh(p.z, p.w));
    }

    // cp.async X chunk 0
    const int xr = t >> 3, xu = (t & 7) * 2;
    const __half* srcX = Xb + (size_t)xr * NPIX + n0 + xu * 8;
    const uint32_t dX = sbX + xr * 272 + xu * 16;
    CPA16(dX, srcX);
    CPA16(dX + 16, srcX + 8);
    CPCOMMIT();

    float acc[2][4][4];
#pragma unroll
    for (int mi = 0; mi < 2; mi++)
#pragma unroll
        for (int nj = 0; nj < 4; nj++)
#pragma unroll
            for (int u = 0; u < 4; u++) acc[mi][nj][u] = 0.f;

    int buf = 0;
#pragma unroll 1
    for (int kt = 0; kt < 6; kt++) {
        if (kt + 1 < 6) {
            const uint32_t bo = (buf ^ 1) * 8704;
            const __half* s2 = srcX + (size_t)(kt + 1) * 32 * NPIX;
            CPA16(dX + bo, s2);
            CPA16(dX + bo + 16, s2 + 8);
            CPCOMMIT();
            CPWAIT(1);
        } else {
            CPWAIT(0);
        }
        __syncthreads();

        const uint32_t bo = buf * 8704;
#pragma unroll
        for (int kk = 0; kk < 32; kk += 16) {
            const int ku = kt * 4 + (kk >> 3);
            unsigned af[2][4], bf[4][2], tmp[4];
#pragma unroll
            for (int mi = 0; mi < 2; mi++)
                ldm_x4(af[mi], sbP + (wm + mi * 16 + lr) * 400 + (ku + lu) * 16);
            {
                const int rowb = kk + lb7 + lb8 * 8;
                const int un = (wn >> 3) + lb16;
                ldm_x4_t(tmp, sbX + bo + rowb * 272 + un * 16);
                bf[0][0] = tmp[0]; bf[0][1] = tmp[1];
                bf[1][0] = tmp[2]; bf[1][1] = tmp[3];
                ldm_x4_t(tmp, sbX + bo + rowb * 272 + (un + 2) * 16);
                bf[2][0] = tmp[0]; bf[2][1] = tmp[1];
                bf[3][0] = tmp[2]; bf[3][1] = tmp[3];
            }
#pragma unroll
            for (int mi = 0; mi < 2; mi++)
#pragma unroll
                for (int nj = 0; nj < 4; nj++)
                    mma_h(acc[mi][nj], af[mi], bf[nj][0], bf[nj][1]);
        }
        __syncthreads();
        buf ^= 1;
    }

    float* Yb = Y + (size_t)b * CCH * NPIX;
#pragma unroll
    for (int mi = 0; mi < 2; mi++)
#pragma unroll
        for (int nj = 0; nj < 4; nj++) {
            const int row = i0 + wm + mi * 16 + g;
            const int col = n0 + wn + nj * 8 + 2 * tg;
            *(float2*)&Yb[(size_t)row * NPIX + col]       = make_float2(acc[mi][nj][0], acc[mi][nj][1]);
            *(float2*)&Yb[(size_t)(row + 8) * NPIX + col] = make_float2(acc[mi][nj][2], acc[mi][nj][3]);
        }
}

// =====================================================================
// Launch
// =====================================================================
extern "C" void kernel_launch(void* const* d_in, const int* in_sizes, int n_in,
                              void* d_out, int out_size) {
    const float* x    = (const float*)d_in[0];
    const float* wqkv = (const float*)d_in[1];
    const float* wout = (const float*)d_in[2];
    const float* temp = (const float*)d_in[3];
    float* y          = (float*)d_out;
    (void)in_sizes; (void)n_in; (void)out_size;

    static bool attr_set = false;
    if (!attr_set) {
        cudaFuncSetAttribute(attn_kernel, cudaFuncAttributeMaxDynamicSharedMemorySize,
                             (int)ATTN_SMEM);
        attr_set = true;
    }

    prep_h<<<24576, 256>>>(x);
    gram_h2<<<dim3(6, SPLIT, BATCH), 128>>>();
    gram_reduce6<<<96, 256>>>();
    attn_kernel<<<dim3(HEADS, BATCH), 192, ATTN_SMEM>>>(wqkv, temp);
    m_kernel<<<576, 256>>>(wout);
    p_kernel<<<dim3(6, 6, BATCH), 256>>>(wqkv);
    y_h2<<<dim3(3, 512, BATCH), 256>>>(y);
}

// round 10
// speedup vs baseline: 1.9667x; 1.2142x over previous
#include <cuda_runtime.h>
#include <cuda_fp16.h>
#include <math.h>
#include <stdint.h>

// Problem constants
#define BATCH 4
#define CCH   192
#define NPIX  65536
#define HEADS 8
#define CH    24
#define SPLIT 32
#define KCH   (NPIX / SPLIT)   // 2048

// ---------------- device scratch (static, no allocation) ----------------
__device__ float g_Spart[BATCH * 6 * SPLIT * 4096];
__device__ float g_S[BATCH * CCH * CCH];
__device__ float g_T[BATCH * 2 * CCH * CCH];        // [b][r<384][m]: Wq·S / Wk·S
__device__ float g_attn[BATCH * HEADS * CH * CH];
__device__ float g_M[BATCH * CCH * CCH];
__device__ float g_P[BATCH * CCH * CCH];
__device__ __align__(16) __half g_Xh[(size_t)BATCH * CCH * NPIX];

// ---------------- helpers ----------------
__device__ __forceinline__ unsigned pkh(float a, float b) {
    __half2 h = __floats2half2_rn(a, b);
    return *reinterpret_cast<unsigned*>(&h);
}
__device__ __forceinline__ uint32_t s2u(const void* p) {
    uint32_t a;
    asm("{.reg .u64 t; cvta.to.shared.u64 t, %1; cvt.u32.u64 %0, t;}" : "=r"(a) : "l"(p));
    return a;
}
__device__ __forceinline__ void mma_h(float* d, const unsigned* a,
                                      unsigned b0, unsigned b1) {
    asm volatile(
        "mma.sync.aligned.m16n8k16.row.col.f32.f16.f16.f32 "
        "{%0,%1,%2,%3}, {%4,%5,%6,%7}, {%8,%9}, {%0,%1,%2,%3};"
        : "+f"(d[0]), "+f"(d[1]), "+f"(d[2]), "+f"(d[3])
        : "r"(a[0]), "r"(a[1]), "r"(a[2]), "r"(a[3]), "r"(b0), "r"(b1));
}
__device__ __forceinline__ void ldm_x4(unsigned* r, uint32_t a) {
    asm volatile("ldmatrix.sync.aligned.m8n8.x4.shared.b16 {%0,%1,%2,%3}, [%4];"
                 : "=r"(r[0]), "=r"(r[1]), "=r"(r[2]), "=r"(r[3]) : "r"(a));
}
__device__ __forceinline__ void ldm_x4_t(unsigned* r, uint32_t a) {
    asm volatile("ldmatrix.sync.aligned.m8n8.x4.trans.shared.b16 {%0,%1,%2,%3}, [%4];"
                 : "=r"(r[0]), "=r"(r[1]), "=r"(r[2]), "=r"(r[3]) : "r"(a));
}
#define CPA16(dst, src) asm volatile("cp.async.cg.shared.global [%0], [%1], 16;" :: "r"(dst), "l"(src))
#define CPCOMMIT()      asm volatile("cp.async.commit_group;")
#define CPWAIT(n)       asm volatile("cp.async.wait_group %0;" :: "n"(n))

__device__ __forceinline__ void tile_pair(int tp, int& ti, int& tj) {
    ti = (tp < 3) ? 0 : ((tp < 5) ? 1 : 2);
    tj = (tp < 3) ? tp : ((tp < 5) ? tp - 2 : 2);
}

// =====================================================================
// Kernel 0: prep X fp32 -> fp16, same layout. grid (24576), 256 thr.
// =====================================================================
__global__ __launch_bounds__(256) void prep_h(const float* __restrict__ X) {
    const size_t g = ((size_t)blockIdx.x * 256 + threadIdx.x) * 8;
    float4 a = *(const float4*)(X + g);
    float4 b = *(const float4*)(X + g + 4);
    uint4 o = make_uint4(pkh(a.x, a.y), pkh(a.z, a.w), pkh(b.x, b.y), pkh(b.z, b.w));
    *(uint4*)(g_Xh + g) = o;
}

// =====================================================================
// Kernel 1: fp16 partial Gram via cp.async + ldmatrix. (unchanged)
// =====================================================================
__global__ __launch_bounds__(128) void gram_h2() {
    const int tp = blockIdx.x, split = blockIdx.y, b = blockIdx.z;
    int ti, tj; tile_pair(tp, ti, tj);

    __shared__ __align__(16) __half As[2][64][72];
    __shared__ __align__(16) __half Bs[2][64][72];
    const uint32_t sbA = s2u(As), sbB = s2u(Bs);

    const int t = threadIdx.x, lane = t & 31, wid = t >> 5;
    const int g = lane >> 2, tg = lane & 3;
    const int lr = lane & 15, lu = lane >> 4;
    const int wm = (wid >> 1) * 32, wn = (wid & 1) * 32;
    const int ldr = t >> 1, ldu = (t & 1) * 4;

    const __half* srcA = g_Xh + ((size_t)(b * CCH + ti * 64 + ldr)) * NPIX + split * KCH + ldu * 8;
    const __half* srcB = g_Xh + ((size_t)(b * CCH + tj * 64 + ldr)) * NPIX + split * KCH + ldu * 8;
    const uint32_t dA = sbA + ldr * 144 + ldu * 16;
    const uint32_t dB = sbB + ldr * 144 + ldu * 16;

    float acc[2][4][4];
#pragma unroll
    for (int mi = 0; mi < 2; mi++)
#pragma unroll
        for (int nj = 0; nj < 4; nj++)
#pragma unroll
            for (int u = 0; u < 4; u++) acc[mi][nj][u] = 0.f;

#pragma unroll
    for (int j = 0; j < 4; j++) {
        CPA16(dA + j * 16, srcA + j * 8);
        CPA16(dB + j * 16, srcB + j * 8);
    }
    CPCOMMIT();

    int buf = 0;
    const int NT = KCH / 64;
#pragma unroll 1
    for (int kt = 0; kt < NT; kt++) {
        if (kt + 1 < NT) {
            const uint32_t bo = (buf ^ 1) * 9216;
#pragma unroll
            for (int j = 0; j < 4; j++) {
                CPA16(dA + bo + j * 16, srcA + (kt + 1) * 64 + j * 8);
                CPA16(dB + bo + j * 16, srcB + (kt + 1) * 64 + j * 8);
            }
            CPCOMMIT();
            CPWAIT(1);
        } else {
            CPWAIT(0);
        }
        __syncthreads();

        const uint32_t bo = buf * 9216;
#pragma unroll
        for (int kk = 0; kk < 64; kk += 16) {
            const uint32_t col = ((kk >> 3) + lu) * 16;
            unsigned af[2][4], bf[4][2], tmp[4];
#pragma unroll
            for (int mi = 0; mi < 2; mi++)
                ldm_x4(af[mi], sbA + bo + (wm + mi * 16 + lr) * 144 + col);
#pragma unroll
            for (int nj2 = 0; nj2 < 2; nj2++) {
                ldm_x4(tmp, sbB + bo + (wn + nj2 * 16 + lr) * 144 + col);
                bf[nj2 * 2][0] = tmp[0]; bf[nj2 * 2][1] = tmp[2];
                bf[nj2 * 2 + 1][0] = tmp[1]; bf[nj2 * 2 + 1][1] = tmp[3];
            }
#pragma unroll
            for (int mi = 0; mi < 2; mi++)
#pragma unroll
                for (int nj = 0; nj < 4; nj++)
                    mma_h(acc[mi][nj], af[mi], bf[nj][0], bf[nj][1]);
        }
        __syncthreads();
        buf ^= 1;
    }

    float* out = g_Spart + ((size_t)((b * 6 + tp) * SPLIT + split) << 12);
#pragma unroll
    for (int mi = 0; mi < 2; mi++)
#pragma unroll
        for (int nj = 0; nj < 4; nj++) {
            const int m0 = wm + mi * 16 + g;
            const int nc = wn + nj * 8 + 2 * tg;
            *(float2*)&out[m0 * 64 + nc]       = make_float2(acc[mi][nj][0], acc[mi][nj][1]);
            *(float2*)&out[(m0 + 8) * 64 + nc] = make_float2(acc[mi][nj][2], acc[mi][nj][3]);
        }
}

// =====================================================================
// Kernel 2: split reduction + mirror. grid(96), 256 thr. (unchanged)
// =====================================================================
__global__ __launch_bounds__(256) void gram_reduce6() {
    const int q = blockIdx.x & 3, blk = blockIdx.x >> 2;
    const int b = blk / 6, tp = blk % 6;
    int ti, tj; tile_pair(tp, ti, tj);
    const float* base = g_Spart + ((size_t)(b * 6 + tp) * SPLIT << 12);
    for (int idx = q * 1024 + threadIdx.x; idx < (q + 1) * 1024; idx += 256) {
        float s = 0.f;
#pragma unroll
        for (int sp = 0; sp < SPLIT; sp++) s += base[(sp << 12) + idx];
        const int i = idx >> 6, j = idx & 63;
        g_S[b * CCH * CCH + (ti * 64 + i) * CCH + (tj * 64 + j)] = s;
        if (ti != tj)
            g_S[b * CCH * CCH + (tj * 64 + j) * CCH + (ti * 64 + i)] = s;
    }
}

// =====================================================================
// Kernel 3a: T = W_qk @ S  (r<384 -> q rows then k rows).
// grid (6 rtiles, 3 mtiles, BATCH), 256 threads, 64x64 tiles, K=192.
// =====================================================================
__global__ __launch_bounds__(256) void qk_kernel(const float* __restrict__ wqkv) {
    const int r0 = blockIdx.x * 64, m0 = blockIdx.y * 64, b = blockIdx.z;
    __shared__ float Ws[64][36], Ss[32][68];
    const int t = threadIdx.x, tx = t & 15, ty = t >> 4;
    const float* Sb = g_S + b * CCH * CCH;

    float acc[4][4];
#pragma unroll
    for (int i = 0; i < 4; i++)
#pragma unroll
        for (int j = 0; j < 4; j++) acc[i][j] = 0.f;

#pragma unroll 1
    for (int k0 = 0; k0 < CCH; k0 += 32) {
#pragma unroll
        for (int i = 0; i < 2; i++) {      // W chunk: 64 x 32
            const int idx = t + i * 256;
            const int r = idx >> 3, c4 = (idx & 7) << 2;
            float4 w = *(const float4*)(wqkv + (r0 + r) * CCH + k0 + c4);
            *(float4*)&Ws[r][c4] = w;
        }
#pragma unroll
        for (int i = 0; i < 2; i++) {      // S chunk: 32 x 64
            const int idx = t + i * 256;
            const int kk = idx >> 4, m4 = (idx & 15) << 2;
            float4 s = *(const float4*)(Sb + (k0 + kk) * CCH + m0 + m4);
            *(float4*)&Ss[kk][m4] = s;
        }
        __syncthreads();
#pragma unroll
        for (int kk = 0; kk < 32; kk++) {
            float av[4], bv[4];
#pragma unroll
            for (int i = 0; i < 4; i++) av[i] = Ws[ty * 4 + i][kk];
            float4 b4 = *(const float4*)&Ss[kk][tx * 4];
            bv[0] = b4.x; bv[1] = b4.y; bv[2] = b4.z; bv[3] = b4.w;
#pragma unroll
            for (int i = 0; i < 4; i++)
#pragma unroll
                for (int j = 0; j < 4; j++)
                    acc[i][j] = fmaf(av[i], bv[j], acc[i][j]);
        }
        __syncthreads();
    }
#pragma unroll
    for (int i = 0; i < 4; i++)
        *(float4*)&g_T[((size_t)b * 384 + r0 + ty * 4 + i) * CCH + m0 + tx * 4] =
            make_float4(acc[i][0], acc[i][1], acc[i][2], acc[i][3]);
}

// =====================================================================
// Kernel 3b: per-(b,h) logits + softmax from precomputed T.
// grid (HEADS, BATCH), 256 threads, dynamic smem.
// =====================================================================
#define SD2 193
#define ATTN2_SMEM ((4 * 24 * SD2 + 576 + 48) * sizeof(float))

__global__ __launch_bounds__(256) void attn2_kernel(const float* __restrict__ wqkv,
                                                    const float* __restrict__ temp) {
    const int h = blockIdx.x, b = blockIdx.y;
    extern __shared__ float smf[];
    float* T1s = smf;
    float* T2s = T1s + 24 * SD2;
    float* Wqs = T2s + 24 * SD2;
    float* Wks = Wqs + 24 * SD2;
    float* Gs  = Wks + 24 * SD2;
    float* nqv = Gs + 576;
    float* nkv = nqv + 24;
    const int tid = threadIdx.x;

    // load T1/T2 rows of this head + Wq/Wk rows
    for (int idx = tid; idx < 24 * 192; idx += 256) {
        const int c = idx / 192, m = idx % 192;
        T1s[c * SD2 + m] = g_T[((size_t)b * 384 + h * CH + c) * CCH + m];
        T2s[c * SD2 + m] = g_T[((size_t)b * 384 + 192 + h * CH + c) * CCH + m];
        Wqs[c * SD2 + m] = wqkv[(h * CH + c) * CCH + m];
        Wks[c * SD2 + m] = wqkv[(CCH + h * CH + c) * CCH + m];
    }
    __syncthreads();

    for (int p = tid; p < 576; p += 256) {
        const int c = p / 24, d = p % 24;
        float gg = 0.f;
        for (int mm = 0; mm < CCH; mm++)
            gg = fmaf(T1s[c * SD2 + mm], Wks[d * SD2 + mm], gg);
        Gs[c * 24 + d] = gg;
    }
    if (tid < 24) {
        float s = 0.f;
        for (int mm = 0; mm < CCH; mm++)
            s = fmaf(T1s[tid * SD2 + mm], Wqs[tid * SD2 + mm], s);
        nqv[tid] = fmaxf(sqrtf(s), 1e-12f);
    } else if (tid < 48) {
        const int c = tid - 24;
        float s = 0.f;
        for (int mm = 0; mm < CCH; mm++)
            s = fmaf(T2s[c * SD2 + mm], Wks[c * SD2 + mm], s);
        nkv[c] = fmaxf(sqrtf(s), 1e-12f);
    }
    __syncthreads();

    if (tid < 24) {
        const int c = tid;
        const float tpv = temp[h];
        float l[24];
        float mx = -1e30f;
#pragma unroll
        for (int d = 0; d < 24; d++) {
            l[d] = Gs[c * 24 + d] * tpv / (nqv[c] * nkv[d]);
            mx = fmaxf(mx, l[d]);
        }
        float s = 0.f;
#pragma unroll
        for (int d = 0; d < 24; d++) { l[d] = expf(l[d] - mx); s += l[d]; }
        const float inv = 1.f / s;
        float* arow = g_attn + ((b * HEADS + h) * CH + c) * CH;
#pragma unroll
        for (int d = 0; d < 24; d++) arow[d] = l[d] * inv;
    }
}

// =====================================================================
// Kernel 4: M = W_out @ blockdiag(attn). grid(576), 256 threads.
// =====================================================================
__global__ __launch_bounds__(256) void m_kernel(const float* __restrict__ wout) {
    const int idx = blockIdx.x * 256 + threadIdx.x;
    const int b = idx / (CCH * CCH);
    const int r = idx % (CCH * CCH);
    const int o = r / CCH, j = r % CCH;
    const int h = j / CH, d = j % CH;
    const float* wrow = wout + o * CCH + h * CH;
    const float* acol = g_attn + ((b * HEADS + h) * CH) * CH + d;
    float s = 0.f;
#pragma unroll
    for (int c = 0; c < CH; c++) s = fmaf(wrow[c], acol[c * CH], s);
    g_M[idx] = s;
}

// =====================================================================
// Kernel 5: P = M @ W_v. grid (6,6,BATCH), 256 threads.
// =====================================================================
__global__ __launch_bounds__(256) void p_kernel(const float* __restrict__ wqkv) {
    const int b = blockIdx.z;
    const int i0 = blockIdx.y * 32, j0 = blockIdx.x * 32;
    __shared__ float Ms[32][33], Ws[32][33];
    const int tid = threadIdx.x;
    const int tx = tid % 32, ty = tid / 32;
    float acc[4] = {0.f, 0.f, 0.f, 0.f};
    const float* Mb = g_M + b * CCH * CCH;
    for (int k0 = 0; k0 < CCH; k0 += 32) {
        const int r0 = tid / 32, kk = tid % 32;
#pragma unroll
        for (int rr = 0; rr < 32; rr += 8) {
            Ms[r0 + rr][kk] = Mb[(i0 + r0 + rr) * CCH + k0 + kk];
            Ws[r0 + rr][kk] = wqkv[(2 * CCH + k0 + r0 + rr) * CCH + j0 + kk];
        }
        __syncthreads();
#pragma unroll
        for (int k2 = 0; k2 < 32; k2++) {
            const float bv = Ws[k2][tx];
#pragma unroll
            for (int u = 0; u < 4; u++)
                acc[u] = fmaf(Ms[ty + 8 * u][k2], bv, acc[u]);
        }
        __syncthreads();
    }
#pragma unroll
    for (int u = 0; u < 4; u++)
        g_P[b * CCH * CCH + (i0 + ty + 8 * u) * CCH + j0 + tx] = acc[u];
}

// =====================================================================
// Kernel 6: Y = P @ X via cp.async + ldmatrix. (unchanged)
// =====================================================================
__global__ __launch_bounds__(256) void y_h2(float* __restrict__ Y) {
    const int b  = blockIdx.z;
    const int i0 = blockIdx.x * 64;
    const int n0 = blockIdx.y * 128;

    __shared__ __align__(16) __half Ps[64][200];
    __shared__ __align__(16) __half Xs[2][32][136];
    const uint32_t sbP = s2u(Ps), sbX = s2u(Xs);

    const int t = threadIdx.x, lane = t & 31, wid = t >> 5;
    const int g = lane >> 2, tg = lane & 3;
    const int lr = lane & 15, lu = lane >> 4;
    const int lb7 = lane & 7, lb8 = (lane >> 3) & 1, lb16 = lane >> 4;
    const int wm = (wid & 1) * 32, wn = (wid >> 1) * 32;

    const float* Pb = g_P + b * CCH * CCH;
    const __half* Xb = g_Xh + (size_t)b * CCH * NPIX;

#pragma unroll
    for (int i = 0; i < 12; i++) {
        const int idx = t + i * 256;
        const int r = idx / 48, c4 = idx % 48;
        float4 p = *(const float4*)(Pb + (i0 + r) * CCH + c4 * 4);
        *(uint2*)&Ps[r][c4 * 4] = make_uint2(pkh(p.x, p.y), pkh(p.z, p.w));
    }

    const int xr = t >> 3, xu = (t & 7) * 2;
    const __half* srcX = Xb + (size_t)xr * NPIX + n0 + xu * 8;
    const uint32_t dX = sbX + xr * 272 + xu * 16;
    CPA16(dX, srcX);
    CPA16(dX + 16, srcX + 8);
    CPCOMMIT();

    float acc[2][4][4];
#pragma unroll
    for (int mi = 0; mi < 2; mi++)
#pragma unroll
        for (int nj = 0; nj < 4; nj++)
#pragma unroll
            for (int u = 0; u < 4; u++) acc[mi][nj][u] = 0.f;

    int buf = 0;
#pragma unroll 1
    for (int kt = 0; kt < 6; kt++) {
        if (kt + 1 < 6) {
            const uint32_t bo = (buf ^ 1) * 8704;
            const __half* s2 = srcX + (size_t)(kt + 1) * 32 * NPIX;
            CPA16(dX + bo, s2);
            CPA16(dX + bo + 16, s2 + 8);
            CPCOMMIT();
            CPWAIT(1);
        } else {
            CPWAIT(0);
        }
        __syncthreads();

        const uint32_t bo = buf * 8704;
#pragma unroll
        for (int kk = 0; kk < 32; kk += 16) {
            const int ku = kt * 4 + (kk >> 3);
            unsigned af[2][4], bf[4][2], tmp[4];
#pragma unroll
            for (int mi = 0; mi < 2; mi++)
                ldm_x4(af[mi], sbP + (wm + mi * 16 + lr) * 400 + (ku + lu) * 16);
            {
                const int rowb = kk + lb7 + lb8 * 8;
                const int un = (wn >> 3) + lb16;
                ldm_x4_t(tmp, sbX + bo + rowb * 272 + un * 16);
                bf[0][0] = tmp[0]; bf[0][1] = tmp[1];
                bf[1][0] = tmp[2]; bf[1][1] = tmp[3];
                ldm_x4_t(tmp, sbX + bo + rowb * 272 + (un + 2) * 16);
                bf[2][0] = tmp[0]; bf[2][1] = tmp[1];
                bf[3][0] = tmp[2]; bf[3][1] = tmp[3];
            }
#pragma unroll
            for (int mi = 0; mi < 2; mi++)
#pragma unroll
                for (int nj = 0; nj < 4; nj++)
                    mma_h(acc[mi][nj], af[mi], bf[nj][0], bf[nj][1]);
        }
        __syncthreads();
        buf ^= 1;
    }

    float* Yb = Y + (size_t)b * CCH * NPIX;
#pragma unroll
    for (int mi = 0; mi < 2; mi++)
#pragma unroll
        for (int nj = 0; nj < 4; nj++) {
            const int row = i0 + wm + mi * 16 + g;
            const int col = n0 + wn + nj * 8 + 2 * tg;
            *(float2*)&Yb[(size_t)row * NPIX + col]       = make_float2(acc[mi][nj][0], acc[mi][nj][1]);
            *(float2*)&Yb[(size_t)(row + 8) * NPIX + col] = make_float2(acc[mi][nj][2], acc[mi][nj][3]);
        }
}

// =====================================================================
// Launch
// =====================================================================
extern "C" void kernel_launch(void* const* d_in, const int* in_sizes, int n_in,
                              void* d_out, int out_size) {
    const float* x    = (const float*)d_in[0];
    const float* wqkv = (const float*)d_in[1];
    const float* wout = (const float*)d_in[2];
    const float* temp = (const float*)d_in[3];
    float* y          = (float*)d_out;
    (void)in_sizes; (void)n_in; (void)out_size;

    static bool attr_set = false;
    if (!attr_set) {
        cudaFuncSetAttribute(attn2_kernel, cudaFuncAttributeMaxDynamicSharedMemorySize,
                             (int)ATTN2_SMEM);
        attr_set = true;
    }

    prep_h<<<24576, 256>>>(x);
    gram_h2<<<dim3(6, SPLIT, BATCH), 128>>>();
    gram_reduce6<<<96, 256>>>();
    qk_kernel<<<dim3(6, 3, BATCH), 256>>>(wqkv);
    attn2_kernel<<<dim3(HEADS, BATCH), 256, ATTN2_SMEM>>>(wqkv, temp);
    m_kernel<<<576, 256>>>(wout);
    p_kernel<<<dim3(6, 6, BATCH), 256>>>(wqkv);
    y_h2<<<dim3(3, 512, BATCH), 256>>>(y);
}

// round 12
// speedup vs baseline: 2.2704x; 1.1544x over previous
#include <cuda_runtime.h>
#include <cuda_fp16.h>
#include <math.h>
#include <stdint.h>

// Problem constants
#define BATCH 4
#define CCH   192
#define NPIX  65536
#define HEADS 8
#define CH    24
#define GSPLIT 64
#define KCH   (NPIX / GSPLIT)   // 1024

// ---------------- device scratch (static, no allocation) ----------------
__device__ float g_Spart[(size_t)BATCH * 6 * GSPLIT * 4096];
__device__ float g_S[BATCH * CCH * CCH];
__device__ float g_T[BATCH * 2 * CCH * CCH];
__device__ float g_attn[BATCH * HEADS * CH * CH];
__device__ float g_P[BATCH * CCH * CCH];
__device__ __align__(16) __half g_Xh[(size_t)BATCH * CCH * NPIX];

// ---------------- helpers ----------------
__device__ __forceinline__ unsigned pkh(float a, float b) {
    __half2 h = __floats2half2_rn(a, b);
    return *reinterpret_cast<unsigned*>(&h);
}
__device__ __forceinline__ uint32_t s2u(const void* p) {
    uint32_t a;
    asm("{.reg .u64 t; cvta.to.shared.u64 t, %1; cvt.u32.u64 %0, t;}" : "=r"(a) : "l"(p));
    return a;
}
__device__ __forceinline__ void mma_h(float* d, const unsigned* a,
                                      unsigned b0, unsigned b1) {
    asm volatile(
        "mma.sync.aligned.m16n8k16.row.col.f32.f16.f16.f32 "
        "{%0,%1,%2,%3}, {%4,%5,%6,%7}, {%8,%9}, {%0,%1,%2,%3};"
        : "+f"(d[0]), "+f"(d[1]), "+f"(d[2]), "+f"(d[3])
        : "r"(a[0]), "r"(a[1]), "r"(a[2]), "r"(a[3]), "r"(b0), "r"(b1));
}
__device__ __forceinline__ void ldm_x4(unsigned* r, uint32_t a) {
    asm volatile("ldmatrix.sync.aligned.m8n8.x4.shared.b16 {%0,%1,%2,%3}, [%4];"
                 : "=r"(r[0]), "=r"(r[1]), "=r"(r[2]), "=r"(r[3]) : "r"(a));
}
__device__ __forceinline__ void ldm_x4_t(unsigned* r, uint32_t a) {
    asm volatile("ldmatrix.sync.aligned.m8n8.x4.trans.shared.b16 {%0,%1,%2,%3}, [%4];"
                 : "=r"(r[0]), "=r"(r[1]), "=r"(r[2]), "=r"(r[3]) : "r"(a));
}
#define CPA16(dst, src) asm volatile("cp.async.cg.shared.global [%0], [%1], 16;" :: "r"(dst), "l"(src))
#define CPCOMMIT()      asm volatile("cp.async.commit_group;")
#define CPWAIT(n)       asm volatile("cp.async.wait_group %0;" :: "n"(n))

__device__ __forceinline__ void tile_pair(int tp, int& ti, int& tj) {
    ti = (tp < 3) ? 0 : ((tp < 5) ? 1 : 2);
    tj = (tp < 3) ? tp : ((tp < 5) ? tp - 2 : 2);
}

// =====================================================================
// Kernel 1: FUSED convert + partial Gram. grid (GSPLIT, BATCH), 256 thr.
// Per block: 192-row x 1024-px strip. Loop 16 chunks of k=64:
//   cp.async fp32 -> F, convert -> fp16 Hb[buf] (+ STG g_Xh), MMA all 6
//   upper-triangle 64x64 tiles (8 warps x 3 warp-tiles of 32x32).
// smem: F 192x68 fp32 (52224 B) + Hb 2 x 192x72 fp16 (55296 B) = 107520 B.
// =====================================================================
#define GF_SMEM 107520

__global__ __launch_bounds__(256) void gram_f(const float* __restrict__ X) {
    extern __shared__ char dsm[];
    float* F = (float*)dsm;
    __half* Hgen = (__half*)(dsm + 52224);       // generic pointer for STS
    const uint32_t sF = s2u(dsm);
    const uint32_t sH = sF + 52224;              // .shared offset for ldmatrix

    const int split = blockIdx.x, b = blockIdx.y;
    const int t = threadIdx.x, lane = t & 31, wid = t >> 5;
    const int g = lane >> 2, tg = lane & 3;
    const int lr = lane & 15, lu = lane >> 4;

    // 3 warp-tiles per warp: wt = wid + j*8 -> (tp, quadrant)
    int abase[3], bbase[3];
#pragma unroll
    for (int j = 0; j < 3; j++) {
        const int wt = wid + j * 8;
        const int tp = wt >> 2, quad = wt & 3;
        int ti, tj; tile_pair(tp, ti, tj);
        abase[j] = ti * 64 + (quad >> 1) * 32;
        bbase[j] = tj * 64 + (quad & 1) * 32;
    }

    const float* Xs0 = X + ((size_t)b * CCH) * NPIX + split * KCH;
    __half* Xh0 = g_Xh + ((size_t)b * CCH) * NPIX + split * KCH;

    float acc[3][2][4][4];
#pragma unroll
    for (int j = 0; j < 3; j++)
#pragma unroll
        for (int mi = 0; mi < 2; mi++)
#pragma unroll
            for (int nj = 0; nj < 4; nj++)
#pragma unroll
                for (int u = 0; u < 4; u++) acc[j][mi][nj][u] = 0.f;

    // prologue: chunk 0 (12 x 16B units per thread-iteration)
#pragma unroll
    for (int i = 0; i < 12; i++) {
        const int unit = t + i * 256;
        const int row = unit >> 4, u16 = unit & 15;
        CPA16(sF + row * 272 + u16 * 16, Xs0 + (size_t)row * NPIX + u16 * 4);
    }
    CPCOMMIT();

#pragma unroll 1
    for (int ch = 0; ch < 16; ch++) {
        CPWAIT(0);
        __syncthreads();

        // convert F -> fp16: 6 units of 8 halves per iteration
        __half* hgen = Hgen + (ch & 1) * 13824;   // 27648 B / 2
        const uint32_t hb = sH + (ch & 1) * 27648;
#pragma unroll
        for (int i = 0; i < 6; i++) {
            const int unit = t + i * 256;
            const int row = unit >> 3, cg = unit & 7;
            float4 v0 = *(const float4*)((const char*)F + row * 272 + cg * 32);
            float4 v1 = *(const float4*)((const char*)F + row * 272 + cg * 32 + 16);
            uint4 o = make_uint4(pkh(v0.x, v0.y), pkh(v0.z, v0.w),
                                 pkh(v1.x, v1.y), pkh(v1.z, v1.w));
            *(uint4*)(hgen + row * 72 + cg * 8) = o;                        // STS (generic)
            *(uint4*)(Xh0 + (size_t)row * NPIX + ch * 64 + cg * 8) = o;     // STG
        }
        __syncthreads();

        if (ch + 1 < 16) {
#pragma unroll
            for (int i = 0; i < 12; i++) {
                const int unit = t + i * 256;
                const int row = unit >> 4, u16 = unit & 15;
                CPA16(sF + row * 272 + u16 * 16,
                      Xs0 + (size_t)row * NPIX + (ch + 1) * 64 + u16 * 4);
            }
            CPCOMMIT();
        }

        // MMA: 4 k16-steps on H[ch&1]
#pragma unroll
        for (int ks = 0; ks < 4; ks++) {
            const uint32_t col = (ks * 2 + lu) * 16;
#pragma unroll
            for (int j = 0; j < 3; j++) {
                unsigned af[2][4], bf[4][2], tmp[4];
#pragma unroll
                for (int mi = 0; mi < 2; mi++)
                    ldm_x4(af[mi], hb + (abase[j] + mi * 16 + lr) * 144 + col);
#pragma unroll
                for (int nj2 = 0; nj2 < 2; nj2++) {
                    ldm_x4(tmp, hb + (bbase[j] + nj2 * 16 + lr) * 144 + col);
                    bf[nj2 * 2][0] = tmp[0]; bf[nj2 * 2][1] = tmp[2];
                    bf[nj2 * 2 + 1][0] = tmp[1]; bf[nj2 * 2 + 1][1] = tmp[3];
                }
#pragma unroll
                for (int mi = 0; mi < 2; mi++)
#pragma unroll
                    for (int nj = 0; nj < 4; nj++)
                        mma_h(acc[j][mi][nj], af[mi], bf[nj][0], bf[nj][1]);
            }
        }
    }

    // epilogue: each warp writes its 3 quadrants
#pragma unroll
    for (int j = 0; j < 3; j++) {
        const int wt = wid + j * 8;
        const int tp = wt >> 2, quad = wt & 3;
        const int qm = (quad >> 1) * 32, qn = (quad & 1) * 32;
        float* out = g_Spart + ((size_t)((b * 6 + tp) * GSPLIT + split) << 12);
#pragma unroll
        for (int mi = 0; mi < 2; mi++)
#pragma unroll
            for (int nj = 0; nj < 4; nj++) {
                const int m0 = qm + mi * 16 + g;
                const int nc = qn + nj * 8 + 2 * tg;
                *(float2*)&out[m0 * 64 + nc]       = make_float2(acc[j][mi][nj][0], acc[j][mi][nj][1]);
                *(float2*)&out[(m0 + 8) * 64 + nc] = make_float2(acc[j][mi][nj][2], acc[j][mi][nj][3]);
            }
    }
}

// =====================================================================
// Kernel 2: split reduction + mirror. grid(192), 256 thr.
// =====================================================================
__global__ __launch_bounds__(256) void gram_reduce6() {
    const int q = blockIdx.x & 7, blk = blockIdx.x >> 3;
    const int b = blk / 6, tp = blk % 6;
    int ti, tj; tile_pair(tp, ti, tj);
    const float* base = g_Spart + ((size_t)(b * 6 + tp) * GSPLIT << 12);
    for (int idx = q * 512 + threadIdx.x; idx < (q + 1) * 512; idx += 256) {
        float s = 0.f;
#pragma unroll
        for (int sp = 0; sp < GSPLIT; sp++) s += base[((size_t)sp << 12) + idx];
        const int i = idx >> 6, j = idx & 63;
        g_S[b * CCH * CCH + (ti * 64 + i) * CCH + (tj * 64 + j)] = s;
        if (ti != tj)
            g_S[b * CCH * CCH + (tj * 64 + j) * CCH + (ti * 64 + i)] = s;
    }
}

// =====================================================================
// Kernel 3a: T = W_qk @ S. grid (12, 3, BATCH), 256 thr, 32x64 tiles.
// =====================================================================
__global__ __launch_bounds__(256) void qk_kernel(const float* __restrict__ wqkv) {
    const int r0 = blockIdx.x * 32, m0 = blockIdx.y * 64, b = blockIdx.z;
    __shared__ float Ws[32][36], Ss[32][68];
    const int t = threadIdx.x, tx = t & 15, ty = t >> 4;
    const float* Sb = g_S + b * CCH * CCH;

    float acc[2][4];
#pragma unroll
    for (int i = 0; i < 2; i++)
#pragma unroll
        for (int j = 0; j < 4; j++) acc[i][j] = 0.f;

#pragma unroll 1
    for (int k0 = 0; k0 < CCH; k0 += 32) {
        {
            const int r = t >> 3, c4 = (t & 7) << 2;
            *(float4*)&Ws[r][c4] = *(const float4*)(wqkv + (r0 + r) * CCH + k0 + c4);
        }
#pragma unroll
        for (int i = 0; i < 2; i++) {
            const int idx = t + i * 256;
            const int kk = idx >> 4, m4 = (idx & 15) << 2;
            *(float4*)&Ss[kk][m4] = *(const float4*)(Sb + (k0 + kk) * CCH + m0 + m4);
        }
        __syncthreads();
#pragma unroll
        for (int kk = 0; kk < 32; kk++) {
            float av0 = Ws[ty * 2][kk], av1 = Ws[ty * 2 + 1][kk];
            float4 b4 = *(const float4*)&Ss[kk][tx * 4];
            acc[0][0] = fmaf(av0, b4.x, acc[0][0]);
            acc[0][1] = fmaf(av0, b4.y, acc[0][1]);
            acc[0][2] = fmaf(av0, b4.z, acc[0][2]);
            acc[0][3] = fmaf(av0, b4.w, acc[0][3]);
            acc[1][0] = fmaf(av1, b4.x, acc[1][0]);
            acc[1][1] = fmaf(av1, b4.y, acc[1][1]);
            acc[1][2] = fmaf(av1, b4.z, acc[1][2]);
            acc[1][3] = fmaf(av1, b4.w, acc[1][3]);
        }
        __syncthreads();
    }
#pragma unroll
    for (int i = 0; i < 2; i++)
        *(float4*)&g_T[((size_t)b * 384 + r0 + ty * 2 + i) * CCH + m0 + tx * 4] =
            make_float4(acc[i][0], acc[i][1], acc[i][2], acc[i][3]);
}

// =====================================================================
// Kernel 3b: per-(b,h) logits + softmax. grid (HEADS, BATCH), 256 thr.
// =====================================================================
#define SD2 193
#define ATTN2_SMEM ((4 * 24 * SD2 + 576 + 48) * sizeof(float))

__global__ __launch_bounds__(256) void attn2_kernel(const float* __restrict__ wqkv,
                                                    const float* __restrict__ temp) {
    const int h = blockIdx.x, b = blockIdx.y;
    extern __shared__ float smf[];
    float* T1s = smf;
    float* T2s = T1s + 24 * SD2;
    float* Wqs = T2s + 24 * SD2;
    float* Wks = Wqs + 24 * SD2;
    float* Gs  = Wks + 24 * SD2;
    float* nqv = Gs + 576;
    float* nkv = nqv + 24;
    const int tid = threadIdx.x;

    for (int idx = tid; idx < 24 * 192; idx += 256) {
        const int c = idx / 192, m = idx % 192;
        T1s[c * SD2 + m] = g_T[((size_t)b * 384 + h * CH + c) * CCH + m];
        T2s[c * SD2 + m] = g_T[((size_t)b * 384 + 192 + h * CH + c) * CCH + m];
        Wqs[c * SD2 + m] = wqkv[(h * CH + c) * CCH + m];
        Wks[c * SD2 + m] = wqkv[(CCH + h * CH + c) * CCH + m];
    }
    __syncthreads();

    for (int p = tid; p < 576; p += 256) {
        const int c = p / 24, d = p % 24;
        float gg = 0.f;
        for (int mm = 0; mm < CCH; mm++)
            gg = fmaf(T1s[c * SD2 + mm], Wks[d * SD2 + mm], gg);
        Gs[c * 24 + d] = gg;
    }
    if (tid < 24) {
        float s = 0.f;
        for (int mm = 0; mm < CCH; mm++)
            s = fmaf(T1s[tid * SD2 + mm], Wqs[tid * SD2 + mm], s);
        nqv[tid] = fmaxf(sqrtf(s), 1e-12f);
    } else if (tid < 48) {
        const int c = tid - 24;
        float s = 0.f;
        for (int mm = 0; mm < CCH; mm++)
            s = fmaf(T2s[c * SD2 + mm], Wks[c * SD2 + mm], s);
        nkv[c] = fmaxf(sqrtf(s), 1e-12f);
    }
    __syncthreads();

    if (tid < 24) {
        const int c = tid;
        const float tpv = temp[h];
        float l[24];
        float mx = -1e30f;
#pragma unroll
        for (int d = 0; d < 24; d++) {
            l[d] = Gs[c * 24 + d] * tpv / (nqv[c] * nkv[d]);
            mx = fmaxf(mx, l[d]);
        }
        float s = 0.f;
#pragma unroll
        for (int d = 0; d < 24; d++) { l[d] = expf(l[d] - mx); s += l[d]; }
        const float inv = 1.f / s;
        float* arow = g_attn + ((b * HEADS + h) * CH + c) * CH;
#pragma unroll
        for (int d = 0; d < 24; d++) arow[d] = l[d] * inv;
    }
}

// =====================================================================
// Kernel 4: FUSED  M = W_out @ blockdiag(attn);  P = M @ W_v.
// grid (6, 6, BATCH), 256 threads.
// =====================================================================
__global__ __launch_bounds__(256) void mp_kernel(const float* __restrict__ wout,
                                                 const float* __restrict__ wqkv) {
    const int b = blockIdx.z;
    const int i0 = blockIdx.y * 32, j0 = blockIdx.x * 32;
    __shared__ float At[HEADS * CH * CH];
    __shared__ float Ms[32][201];
    __shared__ float Ws[32][33];
    const int t = threadIdx.x;

    for (int idx = t; idx < HEADS * CH * CH; idx += 256)
        At[idx] = g_attn[b * HEADS * CH * CH + idx];
    __syncthreads();

    for (int idx = t; idx < 32 * 192; idx += 256) {
        const int mi = idx / 192, k = idx % 192;
        const int h = k / CH, d = k % CH;
        const float* wrow = wout + (i0 + mi) * CCH + h * CH;
        const float* acol = At + h * 576 + d;
        float s = 0.f;
#pragma unroll
        for (int c = 0; c < CH; c++) s = fmaf(wrow[c], acol[c * CH], s);
        Ms[mi][k] = s;
    }
    __syncthreads();

    const int tx = t % 32, ty = t / 32;
    float acc[4] = {0.f, 0.f, 0.f, 0.f};
#pragma unroll 1
    for (int k0 = 0; k0 < CCH; k0 += 32) {
        const int r0 = t / 32, kk = t % 32;
#pragma unroll
        for (int rr = 0; rr < 32; rr += 8)
            Ws[r0 + rr][kk] = wqkv[(2 * CCH + k0 + r0 + rr) * CCH + j0 + kk];
        __syncthreads();
#pragma unroll
        for (int k2 = 0; k2 < 32; k2++) {
            const float bv = Ws[k2][tx];
#pragma unroll
            for (int u = 0; u < 4; u++)
                acc[u] = fmaf(Ms[ty + 8 * u][k0 + k2], bv, acc[u]);
        }
        __syncthreads();
    }
#pragma unroll
    for (int u = 0; u < 4; u++)
        g_P[b * CCH * CCH + (i0 + ty + 8 * u) * CCH + j0 + tx] = acc[u];
}

// =====================================================================
// Kernel 5: Y = P @ X via cp.async + ldmatrix. (unchanged from R10)
// =====================================================================
__global__ __launch_bounds__(256) void y_h2(float* __restrict__ Y) {
    const int b  = blockIdx.z;
    const int i0 = blockIdx.x * 64;
    const int n0 = blockIdx.y * 128;

    __shared__ __align__(16) __half Ps[64][200];
    __shared__ __align__(16) __half Xs[2][32][136];
    const uint32_t sbP = s2u(Ps), sbX = s2u(Xs);

    const int t = threadIdx.x, lane = t & 31, wid = t >> 5;
    const int g = lane >> 2, tg = lane & 3;
    const int lr = lane & 15, lu = lane >> 4;
    const int lb7 = lane & 7, lb8 = (lane >> 3) & 1, lb16 = lane >> 4;
    const int wm = (wid & 1) * 32, wn = (wid >> 1) * 32;

    const float* Pb = g_P + b * CCH * CCH;
    const __half* Xb = g_Xh + (size_t)b * CCH * NPIX;

#pragma unroll
    for (int i = 0; i < 12; i++) {
        const int idx = t + i * 256;
        const int r = idx / 48, c4 = idx % 48;
        float4 p = *(const float4*)(Pb + (i0 + r) * CCH + c4 * 4);
        *(uint2*)&Ps[r][c4 * 4] = make_uint2(pkh(p.x, p.y), pkh(p.z, p.w));
    }

    const int xr = t >> 3, xu = (t & 7) * 2;
    const __half* srcX = Xb + (size_t)xr * NPIX + n0 + xu * 8;
    const uint32_t dX = sbX + xr * 272 + xu * 16;
    CPA16(dX, srcX);
    CPA16(dX + 16, srcX + 8);
    CPCOMMIT();

    float acc[2][4][4];
#pragma unroll
    for (int mi = 0; mi < 2; mi++)
#pragma unroll
        for (int nj = 0; nj < 4; nj++)
#pragma unroll
            for (int u = 0; u < 4; u++) acc[mi][nj][u] = 0.f;

    int buf = 0;
#pragma unroll 1
    for (int kt = 0; kt < 6; kt++) {
        if (kt + 1 < 6) {
            const uint32_t bo = (buf ^ 1) * 8704;
            const __half* s2 = srcX + (size_t)(kt + 1) * 32 * NPIX;
            CPA16(dX + bo, s2);
            CPA16(dX + bo + 16, s2 + 8);
            CPCOMMIT();
            CPWAIT(1);
        } else {
            CPWAIT(0);
        }
        __syncthreads();

        const uint32_t bo = buf * 8704;
#pragma unroll
        for (int kk = 0; kk < 32; kk += 16) {
            const int ku = kt * 4 + (kk >> 3);
            unsigned af[2][4], bf[4][2], tmp[4];
#pragma unroll
            for (int mi = 0; mi < 2; mi++)
                ldm_x4(af[mi], sbP + (wm + mi * 16 + lr) * 400 + (ku + lu) * 16);
            {
                const int rowb = kk + lb7 + lb8 * 8;
                const int un = (wn >> 3) + lb16;
                ldm_x4_t(tmp, sbX + bo + rowb * 272 + un * 16);
                bf[0][0] = tmp[0]; bf[0][1] = tmp[1];
                bf[1][0] = tmp[2]; bf[1][1] = tmp[3];
                ldm_x4_t(tmp, sbX + bo + rowb * 272 + (un + 2) * 16);
                bf[2][0] = tmp[0]; bf[2][1] = tmp[1];
                bf[3][0] = tmp[2]; bf[3][1] = tmp[3];
            }
#pragma unroll
            for (int mi = 0; mi < 2; mi++)
#pragma unroll
                for (int nj = 0; nj < 4; nj++)
                    mma_h(acc[mi][nj], af[mi], bf[nj][0], bf[nj][1]);
        }
        __syncthreads();
        buf ^= 1;
    }

    float* Yb = Y + (size_t)b * CCH * NPIX;
#pragma unroll
    for (int mi = 0; mi < 2; mi++)
#pragma unroll
        for (int nj = 0; nj < 4; nj++) {
            const int row = i0 + wm + mi * 16 + g;
            const int col = n0 + wn + nj * 8 + 2 * tg;
            *(float2*)&Yb[(size_t)row * NPIX + col]       = make_float2(acc[mi][nj][0], acc[mi][nj][1]);
            *(float2*)&Yb[(size_t)(row + 8) * NPIX + col] = make_float2(acc[mi][nj][2], acc[mi][nj][3]);
        }
}

// =====================================================================
// Launch
// =====================================================================
extern "C" void kernel_launch(void* const* d_in, const int* in_sizes, int n_in,
                              void* d_out, int out_size) {
    const float* x    = (const float*)d_in[0];
    const float* wqkv = (const float*)d_in[1];
    const float* wout = (const float*)d_in[2];
    const float* temp = (const float*)d_in[3];
    float* y          = (float*)d_out;
    (void)in_sizes; (void)n_in; (void)out_size;

    static bool attr_set = false;
    if (!attr_set) {
        cudaFuncSetAttribute(gram_f, cudaFuncAttributeMaxDynamicSharedMemorySize, GF_SMEM);
        cudaFuncSetAttribute(attn2_kernel, cudaFuncAttributeMaxDynamicSharedMemorySize,
                             (int)ATTN2_SMEM);
        attr_set = true;
    }

    gram_f<<<dim3(GSPLIT, BATCH), 256, GF_SMEM>>>(x);
    gram_reduce6<<<192, 256>>>();
    qk_kernel<<<dim3(12, 3, BATCH), 256>>>(wqkv);
    attn2_kernel<<<dim3(HEADS, BATCH), 256, ATTN2_SMEM>>>(wqkv, temp);
    mp_kernel<<<dim3(6, 6, BATCH), 256>>>(wout, wqkv);
    y_h2<<<dim3(3, 512, BATCH), 256>>>(y);
}

// round 13
// speedup vs baseline: 2.4141x; 1.0633x over previous
#include <cuda_runtime.h>
#include <cuda_fp16.h>
#include <math.h>
#include <stdint.h>

// Problem constants
#define BATCH 4
#define CCH   192
#define NPIX  65536
#define HEADS 8
#define CH    24
#define GSPLIT 64
#define KCH   (NPIX / GSPLIT)   // 1024

// ---------------- device scratch (static, no allocation) ----------------
__device__ float g_Spart[(size_t)BATCH * 6 * GSPLIT * 4096];
__device__ float g_S[BATCH * CCH * CCH];
__device__ float g_T[BATCH * 2 * CCH * CCH];
__device__ float g_attn[BATCH * HEADS * CH * CH];
__device__ __align__(16) __half g_Ph[BATCH * CCH * CCH];
__device__ __align__(16) __half g_Xh[(size_t)BATCH * CCH * NPIX];

// ---------------- helpers ----------------
__device__ __forceinline__ unsigned pkh(float a, float b) {
    __half2 h = __floats2half2_rn(a, b);
    return *reinterpret_cast<unsigned*>(&h);
}
__device__ __forceinline__ uint32_t s2u(const void* p) {
    uint32_t a;
    asm("{.reg .u64 t; cvta.to.shared.u64 t, %1; cvt.u32.u64 %0, t;}" : "=r"(a) : "l"(p));
    return a;
}
__device__ __forceinline__ void mma_h(float* d, const unsigned* a,
                                      unsigned b0, unsigned b1) {
    asm volatile(
        "mma.sync.aligned.m16n8k16.row.col.f32.f16.f16.f32 "
        "{%0,%1,%2,%3}, {%4,%5,%6,%7}, {%8,%9}, {%0,%1,%2,%3};"
        : "+f"(d[0]), "+f"(d[1]), "+f"(d[2]), "+f"(d[3])
        : "r"(a[0]), "r"(a[1]), "r"(a[2]), "r"(a[3]), "r"(b0), "r"(b1));
}
__device__ __forceinline__ void ldm_x4(unsigned* r, uint32_t a) {
    asm volatile("ldmatrix.sync.aligned.m8n8.x4.shared.b16 {%0,%1,%2,%3}, [%4];"
                 : "=r"(r[0]), "=r"(r[1]), "=r"(r[2]), "=r"(r[3]) : "r"(a));
}
__device__ __forceinline__ void ldm_x4_t(unsigned* r, uint32_t a) {
    asm volatile("ldmatrix.sync.aligned.m8n8.x4.trans.shared.b16 {%0,%1,%2,%3}, [%4];"
                 : "=r"(r[0]), "=r"(r[1]), "=r"(r[2]), "=r"(r[3]) : "r"(a));
}
#define CPA16(dst, src) asm volatile("cp.async.cg.shared.global [%0], [%1], 16;" :: "r"(dst), "l"(src))
#define CPCOMMIT()      asm volatile("cp.async.commit_group;")
#define CPWAIT(n)       asm volatile("cp.async.wait_group %0;" :: "n"(n))

__device__ __forceinline__ void tile_pair(int tp, int& ti, int& tj) {
    ti = (tp < 3) ? 0 : ((tp < 5) ? 1 : 2);
    tj = (tp < 3) ? tp : ((tp < 5) ? tp - 2 : 2);
}

// =====================================================================
// Kernel 1: FUSED convert + partial Gram. grid (GSPLIT, BATCH), 256 thr.
// =====================================================================
#define GF_SMEM 107520

__global__ __launch_bounds__(256) void gram_f(const float* __restrict__ X) {
    extern __shared__ char dsm[];
    float* F = (float*)dsm;
    __half* Hgen = (__half*)(dsm + 52224);
    const uint32_t sF = s2u(dsm);
    const uint32_t sH = sF + 52224;

    const int split = blockIdx.x, b = blockIdx.y;
    const int t = threadIdx.x, lane = t & 31, wid = t >> 5;
    const int g = lane >> 2, tg = lane & 3;
    const int lr = lane & 15, lu = lane >> 4;

    int abase[3], bbase[3];
#pragma unroll
    for (int j = 0; j < 3; j++) {
        const int wt = wid + j * 8;
        const int tp = wt >> 2, quad = wt & 3;
        int ti, tj; tile_pair(tp, ti, tj);
        abase[j] = ti * 64 + (quad >> 1) * 32;
        bbase[j] = tj * 64 + (quad & 1) * 32;
    }

    const float* Xs0 = X + ((size_t)b * CCH) * NPIX + split * KCH;
    __half* Xh0 = g_Xh + ((size_t)b * CCH) * NPIX + split * KCH;

    float acc[3][2][4][4];
#pragma unroll
    for (int j = 0; j < 3; j++)
#pragma unroll
        for (int mi = 0; mi < 2; mi++)
#pragma unroll
            for (int nj = 0; nj < 4; nj++)
#pragma unroll
                for (int u = 0; u < 4; u++) acc[j][mi][nj][u] = 0.f;

#pragma unroll
    for (int i = 0; i < 12; i++) {
        const int unit = t + i * 256;
        const int row = unit >> 4, u16 = unit & 15;
        CPA16(sF + row * 272 + u16 * 16, Xs0 + (size_t)row * NPIX + u16 * 4);
    }
    CPCOMMIT();

#pragma unroll 1
    for (int ch = 0; ch < 16; ch++) {
        CPWAIT(0);
        __syncthreads();

        __half* hgen = Hgen + (ch & 1) * 13824;
        const uint32_t hb = sH + (ch & 1) * 27648;
#pragma unroll
        for (int i = 0; i < 6; i++) {
            const int unit = t + i * 256;
            const int row = unit >> 3, cg = unit & 7;
            float4 v0 = *(const float4*)((const char*)F + row * 272 + cg * 32);
            float4 v1 = *(const float4*)((const char*)F + row * 272 + cg * 32 + 16);
            uint4 o = make_uint4(pkh(v0.x, v0.y), pkh(v0.z, v0.w),
                                 pkh(v1.x, v1.y), pkh(v1.z, v1.w));
            *(uint4*)(hgen + row * 72 + cg * 8) = o;
            *(uint4*)(Xh0 + (size_t)row * NPIX + ch * 64 + cg * 8) = o;
        }
        __syncthreads();

        if (ch + 1 < 16) {
#pragma unroll
            for (int i = 0; i < 12; i++) {
                const int unit = t + i * 256;
                const int row = unit >> 4, u16 = unit & 15;
                CPA16(sF + row * 272 + u16 * 16,
                      Xs0 + (size_t)row * NPIX + (ch + 1) * 64 + u16 * 4);
            }
            CPCOMMIT();
        }

#pragma unroll
        for (int ks = 0; ks < 4; ks++) {
            const uint32_t col = (ks * 2 + lu) * 16;
#pragma unroll
            for (int j = 0; j < 3; j++) {
                unsigned af[2][4], bf[4][2], tmp[4];
#pragma unroll
                for (int mi = 0; mi < 2; mi++)
                    ldm_x4(af[mi], hb + (abase[j] + mi * 16 + lr) * 144 + col);
#pragma unroll
                for (int nj2 = 0; nj2 < 2; nj2++) {
                    ldm_x4(tmp, hb + (bbase[j] + nj2 * 16 + lr) * 144 + col);
                    bf[nj2 * 2][0] = tmp[0]; bf[nj2 * 2][1] = tmp[2];
                    bf[nj2 * 2 + 1][0] = tmp[1]; bf[nj2 * 2 + 1][1] = tmp[3];
                }
#pragma unroll
                for (int mi = 0; mi < 2; mi++)
#pragma unroll
                    for (int nj = 0; nj < 4; nj++)
                        mma_h(acc[j][mi][nj], af[mi], bf[nj][0], bf[nj][1]);
            }
        }
    }

#pragma unroll
    for (int j = 0; j < 3; j++) {
        const int wt = wid + j * 8;
        const int tp = wt >> 2, quad = wt & 3;
        const int qm = (quad >> 1) * 32, qn = (quad & 1) * 32;
        float* out = g_Spart + ((size_t)((b * 6 + tp) * GSPLIT + split) << 12);
#pragma unroll
        for (int mi = 0; mi < 2; mi++)
#pragma unroll
            for (int nj = 0; nj < 4; nj++) {
                const int m0 = qm + mi * 16 + g;
                const int nc = qn + nj * 8 + 2 * tg;
                *(float2*)&out[m0 * 64 + nc]       = make_float2(acc[j][mi][nj][0], acc[j][mi][nj][1]);
                *(float2*)&out[(m0 + 8) * 64 + nc] = make_float2(acc[j][mi][nj][2], acc[j][mi][nj][3]);
            }
    }
}

// =====================================================================
// Kernel 2: split reduction + mirror. grid(192), 256 thr.
// =====================================================================
__global__ __launch_bounds__(256) void gram_reduce6() {
    const int q = blockIdx.x & 7, blk = blockIdx.x >> 3;
    const int b = blk / 6, tp = blk % 6;
    int ti, tj; tile_pair(tp, ti, tj);
    const float* base = g_Spart + ((size_t)(b * 6 + tp) * GSPLIT << 12);
    for (int idx = q * 512 + threadIdx.x; idx < (q + 1) * 512; idx += 256) {
        float s = 0.f;
#pragma unroll
        for (int sp = 0; sp < GSPLIT; sp++) s += base[((size_t)sp << 12) + idx];
        const int i = idx >> 6, j = idx & 63;
        g_S[b * CCH * CCH + (ti * 64 + i) * CCH + (tj * 64 + j)] = s;
        if (ti != tj)
            g_S[b * CCH * CCH + (tj * 64 + j) * CCH + (ti * 64 + i)] = s;
    }
}

// =====================================================================
// Kernel 3a: T = W_qk @ S. grid (12, 3, BATCH), 256 thr, 32x64 tiles.
// =====================================================================
__global__ __launch_bounds__(256) void qk_kernel(const float* __restrict__ wqkv) {
    const int r0 = blockIdx.x * 32, m0 = blockIdx.y * 64, b = blockIdx.z;
    __shared__ float Ws[32][36], Ss[32][68];
    const int t = threadIdx.x, tx = t & 15, ty = t >> 4;
    const float* Sb = g_S + b * CCH * CCH;

    float acc[2][4];
#pragma unroll
    for (int i = 0; i < 2; i++)
#pragma unroll
        for (int j = 0; j < 4; j++) acc[i][j] = 0.f;

#pragma unroll 1
    for (int k0 = 0; k0 < CCH; k0 += 32) {
        {
            const int r = t >> 3, c4 = (t & 7) << 2;
            *(float4*)&Ws[r][c4] = *(const float4*)(wqkv + (r0 + r) * CCH + k0 + c4);
        }
#pragma unroll
        for (int i = 0; i < 2; i++) {
            const int idx = t + i * 256;
            const int kk = idx >> 4, m4 = (idx & 15) << 2;
            *(float4*)&Ss[kk][m4] = *(const float4*)(Sb + (k0 + kk) * CCH + m0 + m4);
        }
        __syncthreads();
#pragma unroll
        for (int kk = 0; kk < 32; kk++) {
            float av0 = Ws[ty * 2][kk], av1 = Ws[ty * 2 + 1][kk];
            float4 b4 = *(const float4*)&Ss[kk][tx * 4];
            acc[0][0] = fmaf(av0, b4.x, acc[0][0]);
            acc[0][1] = fmaf(av0, b4.y, acc[0][1]);
            acc[0][2] = fmaf(av0, b4.z, acc[0][2]);
            acc[0][3] = fmaf(av0, b4.w, acc[0][3]);
            acc[1][0] = fmaf(av1, b4.x, acc[1][0]);
            acc[1][1] = fmaf(av1, b4.y, acc[1][1]);
            acc[1][2] = fmaf(av1, b4.z, acc[1][2]);
            acc[1][3] = fmaf(av1, b4.w, acc[1][3]);
        }
        __syncthreads();
    }
#pragma unroll
    for (int i = 0; i < 2; i++)
        *(float4*)&g_T[((size_t)b * 384 + r0 + ty * 2 + i) * CCH + m0 + tx * 4] =
            make_float4(acc[i][0], acc[i][1], acc[i][2], acc[i][3]);
}

// =====================================================================
// Kernel 3b: attn3 — warp-per-row logits + softmax.
// grid (HEADS, BATCH), 768 threads (24 warps; warp c handles row c).
// =====================================================================
__global__ __launch_bounds__(768) void attn3(const float* __restrict__ wqkv,
                                             const float* __restrict__ temp) {
    const int h = blockIdx.x, b = blockIdx.y;
    __shared__ float Wks[24][193];
    __shared__ float nks[24];
    const int t = threadIdx.x, lane = t & 31, c = t >> 5;

    for (int idx = t; idx < 24 * 192; idx += 768) {
        const int r = idx / 192, m = idx % 192;
        Wks[r][m] = wqkv[(CCH + h * CH + r) * CCH + m];
    }

    float t1[6], t2[6], wq[6];
    const float* T1r = g_T + ((size_t)b * 384 + h * CH + c) * CCH;
    const float* T2r = g_T + ((size_t)b * 384 + 192 + h * CH + c) * CCH;
    const float* Wqr = wqkv + (h * CH + c) * CCH;
#pragma unroll
    for (int j = 0; j < 6; j++) {
        t1[j] = T1r[lane + 32 * j];
        t2[j] = T2r[lane + 32 * j];
        wq[j] = Wqr[lane + 32 * j];
    }
    __syncthreads();

    // nq (local), nk[c] (to smem)
    float sq = 0.f, sk = 0.f;
#pragma unroll
    for (int j = 0; j < 6; j++) {
        sq = fmaf(t1[j], wq[j], sq);
        sk = fmaf(t2[j], Wks[c][lane + 32 * j], sk);
    }
#pragma unroll
    for (int o = 16; o; o >>= 1) {
        sq += __shfl_xor_sync(0xFFFFFFFFu, sq, o);
        sk += __shfl_xor_sync(0xFFFFFFFFu, sk, o);
    }
    const float nq = fmaxf(sqrtf(sq), 1e-12f);
    if (lane == 0) nks[c] = fmaxf(sqrtf(sk), 1e-12f);

    // G row: after loop, lane d holds G[c][d]
    float gval = 0.f;
#pragma unroll 1
    for (int d = 0; d < 24; d++) {
        float s = 0.f;
#pragma unroll
        for (int j = 0; j < 6; j++)
            s = fmaf(t1[j], Wks[d][lane + 32 * j], s);
#pragma unroll
        for (int o = 16; o; o >>= 1) s += __shfl_xor_sync(0xFFFFFFFFu, s, o);
        if (lane == d) gval = s;
    }
    __syncthreads();

    // warp-local softmax over lanes 0..23
    const float tp = temp[h];
    const float nk = (lane < 24) ? nks[lane] : 1.f;
    float l = (lane < 24) ? gval * tp / (nq * nk) : -1e30f;
    float mx = l;
#pragma unroll
    for (int o = 16; o; o >>= 1) mx = fmaxf(mx, __shfl_xor_sync(0xFFFFFFFFu, mx, o));
    const float e = (lane < 24) ? expf(l - mx) : 0.f;
    float ssum = e;
#pragma unroll
    for (int o = 16; o; o >>= 1) ssum += __shfl_xor_sync(0xFFFFFFFFu, ssum, o);
    if (lane < 24)
        g_attn[((b * HEADS + h) * CH + c) * CH + lane] = e / ssum;
}

// =====================================================================
// Kernel 4: FUSED  M = W_out @ blockdiag(attn);  P = M @ W_v  -> fp16.
// grid (6, 6, BATCH), 256 threads.
// =====================================================================
__global__ __launch_bounds__(256) void mp_kernel(const float* __restrict__ wout,
                                                 const float* __restrict__ wqkv) {
    const int b = blockIdx.z;
    const int i0 = blockIdx.y * 32, j0 = blockIdx.x * 32;
    __shared__ float At[HEADS * CH * CH];
    __shared__ float Ms[32][201];
    __shared__ float Ws[32][33];
    const int t = threadIdx.x;

    for (int idx = t; idx < HEADS * CH * CH; idx += 256)
        At[idx] = g_attn[b * HEADS * CH * CH + idx];
    __syncthreads();

    for (int idx = t; idx < 32 * 192; idx += 256) {
        const int mi = idx / 192, k = idx % 192;
        const int h = k / CH, d = k % CH;
        const float* wrow = wout + (i0 + mi) * CCH + h * CH;
        const float* acol = At + h * 576 + d;
        float s = 0.f;
#pragma unroll
        for (int c = 0; c < CH; c++) s = fmaf(wrow[c], acol[c * CH], s);
        Ms[mi][k] = s;
    }
    __syncthreads();

    const int tx = t % 32, ty = t / 32;
    float acc[4] = {0.f, 0.f, 0.f, 0.f};
#pragma unroll 1
    for (int k0 = 0; k0 < CCH; k0 += 32) {
        const int r0 = t / 32, kk = t % 32;
#pragma unroll
        for (int rr = 0; rr < 32; rr += 8)
            Ws[r0 + rr][kk] = wqkv[(2 * CCH + k0 + r0 + rr) * CCH + j0 + kk];
        __syncthreads();
#pragma unroll
        for (int k2 = 0; k2 < 32; k2++) {
            const float bv = Ws[k2][tx];
#pragma unroll
            for (int u = 0; u < 4; u++)
                acc[u] = fmaf(Ms[ty + 8 * u][k0 + k2], bv, acc[u]);
        }
        __syncthreads();
    }
#pragma unroll
    for (int u = 0; u < 4; u++)
        g_Ph[b * CCH * CCH + (i0 + ty + 8 * u) * CCH + j0 + tx] = __float2half(acc[u]);
}

// =====================================================================
// Kernel 5: Y = P @ X via cp.async + ldmatrix. P now fp16 in gmem.
// grid (3, 512, BATCH), 256 threads.
// =====================================================================
__global__ __launch_bounds__(256) void y_h2(float* __restrict__ Y) {
    const int b  = blockIdx.z;
    const int i0 = blockIdx.x * 64;
    const int n0 = blockIdx.y * 128;

    __shared__ __align__(16) __half Ps[64][200];
    __shared__ __align__(16) __half Xs[2][32][136];
    const uint32_t sbP = s2u(Ps), sbX = s2u(Xs);

    const int t = threadIdx.x, lane = t & 31, wid = t >> 5;
    const int g = lane >> 2, tg = lane & 3;
    const int lr = lane & 15, lu = lane >> 4;
    const int lb7 = lane & 7, lb8 = (lane >> 3) & 1, lb16 = lane >> 4;
    const int wm = (wid & 1) * 32, wn = (wid >> 1) * 32;

    const __half* Pbh = g_Ph + b * CCH * CCH;
    const __half* Xb = g_Xh + (size_t)b * CCH * NPIX;

    // copy P tile (fp16, 64 x 192) into smem: 1536 16B units
#pragma unroll
    for (int i = 0; i < 6; i++) {
        const int idx = t + i * 256;
        const int r = idx / 24, c16 = idx % 24;
        *(uint4*)&Ps[r][c16 * 8] = *(const uint4*)(Pbh + (i0 + r) * CCH + c16 * 8);
    }

    const int xr = t >> 3, xu = (t & 7) * 2;
    const __half* srcX = Xb + (size_t)xr * NPIX + n0 + xu * 8;
    const uint32_t dX = sbX + xr * 272 + xu * 16;
    CPA16(dX, srcX);
    CPA16(dX + 16, srcX + 8);
    CPCOMMIT();

    float acc[2][4][4];
#pragma unroll
    for (int mi = 0; mi < 2; mi++)
#pragma unroll
        for (int nj = 0; nj < 4; nj++)
#pragma unroll
            for (int u = 0; u < 4; u++) acc[mi][nj][u] = 0.f;

    int buf = 0;
#pragma unroll 1
    for (int kt = 0; kt < 6; kt++) {
        if (kt + 1 < 6) {
            const uint32_t bo = (buf ^ 1) * 8704;
            const __half* s2 = srcX + (size_t)(kt + 1) * 32 * NPIX;
            CPA16(dX + bo, s2);
            CPA16(dX + bo + 16, s2 + 8);
            CPCOMMIT();
            CPWAIT(1);
        } else {
            CPWAIT(0);
        }
        __syncthreads();

        const uint32_t bo = buf * 8704;
#pragma unroll
        for (int kk = 0; kk < 32; kk += 16) {
            const int ku = kt * 4 + (kk >> 3);
            unsigned af[2][4], bf[4][2], tmp[4];
#pragma unroll
            for (int mi = 0; mi < 2; mi++)
                ldm_x4(af[mi], sbP + (wm + mi * 16 + lr) * 400 + (ku + lu) * 16);
            {
                const int rowb = kk + lb7 + lb8 * 8;
                const int un = (wn >> 3) + lb16;
                ldm_x4_t(tmp, sbX + bo + rowb * 272 + un * 16);
                bf[0][0] = tmp[0]; bf[0][1] = tmp[1];
                bf[1][0] = tmp[2]; bf[1][1] = tmp[3];
                ldm_x4_t(tmp, sbX + bo + rowb * 272 + (un + 2) * 16);
                bf[2][0] = tmp[0]; bf[2][1] = tmp[1];
                bf[3][0] = tmp[2]; bf[3][1] = tmp[3];
            }
#pragma unroll
            for (int mi = 0; mi < 2; mi++)
#pragma unroll
                for (int nj = 0; nj < 4; nj++)
                    mma_h(acc[mi][nj], af[mi], bf[nj][0], bf[nj][1]);
        }
        __syncthreads();
        buf ^= 1;
    }

    float* Yb = Y + (size_t)b * CCH * NPIX;
#pragma unroll
    for (int mi = 0; mi < 2; mi++)
#pragma unroll
        for (int nj = 0; nj < 4; nj++) {
            const int row = i0 + wm + mi * 16 + g;
            const int col = n0 + wn + nj * 8 + 2 * tg;
            *(float2*)&Yb[(size_t)row * NPIX + col]       = make_float2(acc[mi][nj][0], acc[mi][nj][1]);
            *(float2*)&Yb[(size_t)(row + 8) * NPIX + col] = make_float2(acc[mi][nj][2], acc[mi][nj][3]);
        }
}

// =====================================================================
// Launch
// =====================================================================
extern "C" void kernel_launch(void* const* d_in, const int* in_sizes, int n_in,
                              void* d_out, int out_size) {
    const float* x    = (const float*)d_in[0];
    const float* wqkv = (const float*)d_in[1];
    const float* wout = (const float*)d_in[2];
    const float* temp = (const float*)d_in[3];
    float* y          = (float*)d_out;
    (void)in_sizes; (void)n_in; (void)out_size;

    static bool attr_set = false;
    if (!attr_set) {
        cudaFuncSetAttribute(gram_f, cudaFuncAttributeMaxDynamicSharedMemorySize, GF_SMEM);
        attr_set = true;
    }

    gram_f<<<dim3(GSPLIT, BATCH), 256, GF_SMEM>>>(x);
    gram_reduce6<<<192, 256>>>();
    qk_kernel<<<dim3(12, 3, BATCH), 256>>>(wqkv);
    attn3<<<dim3(HEADS, BATCH), 768>>>(wqkv, temp);
    mp_kernel<<<dim3(6, 6, BATCH), 256>>>(wout, wqkv);
    y_h2<<<dim3(3, 512, BATCH), 256>>>(y);
}

// round 14
// speedup vs baseline: 2.4696x; 1.0230x over previous
#include <cuda_runtime.h>
#include <cuda_fp16.h>
#include <math.h>
#include <stdint.h>

// Problem constants
#define BATCH 4
#define CCH   192
#define NPIX  65536
#define HEADS 8
#define CH    24
#define GSPLIT 74
#define NCHUNK 1024            // total 64-px chunks per (b) strip

// ---------------- device scratch (static, no allocation) ----------------
__device__ float g_Spart[(size_t)BATCH * 6 * GSPLIT * 4096];
__device__ float g_S[BATCH * CCH * CCH];
__device__ float g_T[BATCH * 2 * CCH * CCH];
__device__ float g_attn[BATCH * HEADS * CH * CH];
__device__ __align__(16) __half g_Ph[BATCH * CCH * CCH];
__device__ __align__(16) __half g_Xh[(size_t)BATCH * CCH * NPIX];

// ---------------- helpers ----------------
__device__ __forceinline__ unsigned pkh(float a, float b) {
    __half2 h = __floats2half2_rn(a, b);
    return *reinterpret_cast<unsigned*>(&h);
}
__device__ __forceinline__ uint32_t s2u(const void* p) {
    uint32_t a;
    asm("{.reg .u64 t; cvta.to.shared.u64 t, %1; cvt.u32.u64 %0, t;}" : "=r"(a) : "l"(p));
    return a;
}
__device__ __forceinline__ void mma_h(float* d, const unsigned* a,
                                      unsigned b0, unsigned b1) {
    asm volatile(
        "mma.sync.aligned.m16n8k16.row.col.f32.f16.f16.f32 "
        "{%0,%1,%2,%3}, {%4,%5,%6,%7}, {%8,%9}, {%0,%1,%2,%3};"
        : "+f"(d[0]), "+f"(d[1]), "+f"(d[2]), "+f"(d[3])
        : "r"(a[0]), "r"(a[1]), "r"(a[2]), "r"(a[3]), "r"(b0), "r"(b1));
}
__device__ __forceinline__ void ldm_x4(unsigned* r, uint32_t a) {
    asm volatile("ldmatrix.sync.aligned.m8n8.x4.shared.b16 {%0,%1,%2,%3}, [%4];"
                 : "=r"(r[0]), "=r"(r[1]), "=r"(r[2]), "=r"(r[3]) : "r"(a));
}
__device__ __forceinline__ void ldm_x4_t(unsigned* r, uint32_t a) {
    asm volatile("ldmatrix.sync.aligned.m8n8.x4.trans.shared.b16 {%0,%1,%2,%3}, [%4];"
                 : "=r"(r[0]), "=r"(r[1]), "=r"(r[2]), "=r"(r[3]) : "r"(a));
}
#define CPA16(dst, src) asm volatile("cp.async.cg.shared.global [%0], [%1], 16;" :: "r"(dst), "l"(src))
#define CPCOMMIT()      asm volatile("cp.async.commit_group;")
#define CPWAIT(n)       asm volatile("cp.async.wait_group %0;" :: "n"(n))

__device__ __forceinline__ void tile_pair(int tp, int& ti, int& tj) {
    ti = (tp < 3) ? 0 : ((tp < 5) ? 1 : 2);
    tj = (tp < 3) ? tp : ((tp < 5) ? tp - 2 : 2);
}

// =====================================================================
// Kernel 1: FUSED convert + partial Gram. grid (GSPLIT, BATCH), 256 thr.
// 296 CTAs = one full 2-CTA/SM wave on 148 SMs. Block sp handles chunks
// [1024*sp/74, 1024*(sp+1)/74) of 64 px each (13 or 14 chunks).
// =====================================================================
#define GF_SMEM 107520

__global__ __launch_bounds__(256) void gram_f(const float* __restrict__ X) {
    extern __shared__ char dsm[];
    float* F = (float*)dsm;
    __half* Hgen = (__half*)(dsm + 52224);
    const uint32_t sF = s2u(dsm);
    const uint32_t sH = sF + 52224;

    const int split = blockIdx.x, b = blockIdx.y;
    const int c0 = (split * NCHUNK) / GSPLIT;
    const int nch = ((split + 1) * NCHUNK) / GSPLIT - c0;
    const int t = threadIdx.x, lane = t & 31, wid = t >> 5;
    const int g = lane >> 2, tg = lane & 3;
    const int lr = lane & 15, lu = lane >> 4;

    int abase[3], bbase[3];
#pragma unroll
    for (int j = 0; j < 3; j++) {
        const int wt = wid + j * 8;
        const int tp = wt >> 2, quad = wt & 3;
        int ti, tj; tile_pair(tp, ti, tj);
        abase[j] = ti * 64 + (quad >> 1) * 32;
        bbase[j] = tj * 64 + (quad & 1) * 32;
    }

    const float* Xs0 = X + ((size_t)b * CCH) * NPIX + c0 * 64;
    __half* Xh0 = g_Xh + ((size_t)b * CCH) * NPIX + c0 * 64;

    float acc[3][2][4][4];
#pragma unroll
    for (int j = 0; j < 3; j++)
#pragma unroll
        for (int mi = 0; mi < 2; mi++)
#pragma unroll
            for (int nj = 0; nj < 4; nj++)
#pragma unroll
                for (int u = 0; u < 4; u++) acc[j][mi][nj][u] = 0.f;

#pragma unroll
    for (int i = 0; i < 12; i++) {
        const int unit = t + i * 256;
        const int row = unit >> 4, u16 = unit & 15;
        CPA16(sF + row * 272 + u16 * 16, Xs0 + (size_t)row * NPIX + u16 * 4);
    }
    CPCOMMIT();

#pragma unroll 1
    for (int ch = 0; ch < nch; ch++) {
        CPWAIT(0);
        __syncthreads();

        __half* hgen = Hgen + (ch & 1) * 13824;
        const uint32_t hb = sH + (ch & 1) * 27648;
#pragma unroll
        for (int i = 0; i < 6; i++) {
            const int unit = t + i * 256;
            const int row = unit >> 3, cg = unit & 7;
            float4 v0 = *(const float4*)((const char*)F + row * 272 + cg * 32);
            float4 v1 = *(const float4*)((const char*)F + row * 272 + cg * 32 + 16);
            uint4 o = make_uint4(pkh(v0.x, v0.y), pkh(v0.z, v0.w),
                                 pkh(v1.x, v1.y), pkh(v1.z, v1.w));
            *(uint4*)(hgen + row * 72 + cg * 8) = o;
            *(uint4*)(Xh0 + (size_t)row * NPIX + ch * 64 + cg * 8) = o;
        }
        __syncthreads();

        if (ch + 1 < nch) {
#pragma unroll
            for (int i = 0; i < 12; i++) {
                const int unit = t + i * 256;
                const int row = unit >> 4, u16 = unit & 15;
                CPA16(sF + row * 272 + u16 * 16,
                      Xs0 + (size_t)row * NPIX + (ch + 1) * 64 + u16 * 4);
            }
            CPCOMMIT();
        }

#pragma unroll
        for (int ks = 0; ks < 4; ks++) {
            const uint32_t col = (ks * 2 + lu) * 16;
#pragma unroll
            for (int j = 0; j < 3; j++) {
                unsigned af[2][4], bf[4][2], tmp[4];
#pragma unroll
                for (int mi = 0; mi < 2; mi++)
                    ldm_x4(af[mi], hb + (abase[j] + mi * 16 + lr) * 144 + col);
#pragma unroll
                for (int nj2 = 0; nj2 < 2; nj2++) {
                    ldm_x4(tmp, hb + (bbase[j] + nj2 * 16 + lr) * 144 + col);
                    bf[nj2 * 2][0] = tmp[0]; bf[nj2 * 2][1] = tmp[2];
                    bf[nj2 * 2 + 1][0] = tmp[1]; bf[nj2 * 2 + 1][1] = tmp[3];
                }
#pragma unroll
                for (int mi = 0; mi < 2; mi++)
#pragma unroll
                    for (int nj = 0; nj < 4; nj++)
                        mma_h(acc[j][mi][nj], af[mi], bf[nj][0], bf[nj][1]);
            }
        }
    }

#pragma unroll
    for (int j = 0; j < 3; j++) {
        const int wt = wid + j * 8;
        const int tp = wt >> 2, quad = wt & 3;
        const int qm = (quad >> 1) * 32, qn = (quad & 1) * 32;
        float* out = g_Spart + ((size_t)((b * 6 + tp) * GSPLIT + split) << 12);
#pragma unroll
        for (int mi = 0; mi < 2; mi++)
#pragma unroll
            for (int nj = 0; nj < 4; nj++) {
                const int m0 = qm + mi * 16 + g;
                const int nc = qn + nj * 8 + 2 * tg;
                *(float2*)&out[m0 * 64 + nc]       = make_float2(acc[j][mi][nj][0], acc[j][mi][nj][1]);
                *(float2*)&out[(m0 + 8) * 64 + nc] = make_float2(acc[j][mi][nj][2], acc[j][mi][nj][3]);
            }
    }
}

// =====================================================================
// Kernel 2: split reduction + mirror. grid(192), 256 thr.
// =====================================================================
__global__ __launch_bounds__(256) void gram_reduce6() {
    const int q = blockIdx.x & 7, blk = blockIdx.x >> 3;
    const int b = blk / 6, tp = blk % 6;
    int ti, tj; tile_pair(tp, ti, tj);
    const float* base = g_Spart + ((size_t)(b * 6 + tp) * GSPLIT << 12);
    for (int idx = q * 512 + threadIdx.x; idx < (q + 1) * 512; idx += 256) {
        float s = 0.f;
#pragma unroll
        for (int sp = 0; sp < GSPLIT; sp++) s += base[((size_t)sp << 12) + idx];
        const int i = idx >> 6, j = idx & 63;
        g_S[b * CCH * CCH + (ti * 64 + i) * CCH + (tj * 64 + j)] = s;
        if (ti != tj)
            g_S[b * CCH * CCH + (tj * 64 + j) * CCH + (ti * 64 + i)] = s;
    }
}

// =====================================================================
// Kernel 3a: T = W_qk @ S. grid (12, 3, BATCH), 256 thr, 32x64 tiles.
// =====================================================================
__global__ __launch_bounds__(256) void qk_kernel(const float* __restrict__ wqkv) {
    const int r0 = blockIdx.x * 32, m0 = blockIdx.y * 64, b = blockIdx.z;
    __shared__ float Ws[32][36], Ss[32][68];
    const int t = threadIdx.x, tx = t & 15, ty = t >> 4;
    const float* Sb = g_S + b * CCH * CCH;

    float acc[2][4];
#pragma unroll
    for (int i = 0; i < 2; i++)
#pragma unroll
        for (int j = 0; j < 4; j++) acc[i][j] = 0.f;

#pragma unroll 1
    for (int k0 = 0; k0 < CCH; k0 += 32) {
        {
            const int r = t >> 3, c4 = (t & 7) << 2;
            *(float4*)&Ws[r][c4] = *(const float4*)(wqkv + (r0 + r) * CCH + k0 + c4);
        }
#pragma unroll
        for (int i = 0; i < 2; i++) {
            const int idx = t + i * 256;
            const int kk = idx >> 4, m4 = (idx & 15) << 2;
            *(float4*)&Ss[kk][m4] = *(const float4*)(Sb + (k0 + kk) * CCH + m0 + m4);
        }
        __syncthreads();
#pragma unroll
        for (int kk = 0; kk < 32; kk++) {
            float av0 = Ws[ty * 2][kk], av1 = Ws[ty * 2 + 1][kk];
            float4 b4 = *(const float4*)&Ss[kk][tx * 4];
            acc[0][0] = fmaf(av0, b4.x, acc[0][0]);
            acc[0][1] = fmaf(av0, b4.y, acc[0][1]);
            acc[0][2] = fmaf(av0, b4.z, acc[0][2]);
            acc[0][3] = fmaf(av0, b4.w, acc[0][3]);
            acc[1][0] = fmaf(av1, b4.x, acc[1][0]);
            acc[1][1] = fmaf(av1, b4.y, acc[1][1]);
            acc[1][2] = fmaf(av1, b4.z, acc[1][2]);
            acc[1][3] = fmaf(av1, b4.w, acc[1][3]);
        }
        __syncthreads();
    }
#pragma unroll
    for (int i = 0; i < 2; i++)
        *(float4*)&g_T[((size_t)b * 384 + r0 + ty * 2 + i) * CCH + m0 + tx * 4] =
            make_float4(acc[i][0], acc[i][1], acc[i][2], acc[i][3]);
}

// =====================================================================
// Kernel 3b: attn3 — warp-per-row logits + softmax, d-loop fully
// unrolled so the 24 shuffle-reduction chains overlap.
// grid (HEADS, BATCH), 768 threads.
// =====================================================================
__global__ __launch_bounds__(768) void attn3(const float* __restrict__ wqkv,
                                             const float* __restrict__ temp) {
    const int h = blockIdx.x, b = blockIdx.y;
    __shared__ float Wks[24][193];
    __shared__ float nks[24];
    const int t = threadIdx.x, lane = t & 31, c = t >> 5;

    for (int idx = t; idx < 24 * 192; idx += 768) {
        const int r = idx / 192, m = idx % 192;
        Wks[r][m] = wqkv[(CCH + h * CH + r) * CCH + m];
    }

    float t1[6], t2[6], wq[6];
    const float* T1r = g_T + ((size_t)b * 384 + h * CH + c) * CCH;
    const float* T2r = g_T + ((size_t)b * 384 + 192 + h * CH + c) * CCH;
    const float* Wqr = wqkv + (h * CH + c) * CCH;
#pragma unroll
    for (int j = 0; j < 6; j++) {
        t1[j] = T1r[lane + 32 * j];
        t2[j] = T2r[lane + 32 * j];
        wq[j] = Wqr[lane + 32 * j];
    }
    __syncthreads();

    float sq = 0.f, sk = 0.f;
#pragma unroll
    for (int j = 0; j < 6; j++) {
        sq = fmaf(t1[j], wq[j], sq);
        sk = fmaf(t2[j], Wks[c][lane + 32 * j], sk);
    }
#pragma unroll
    for (int o = 16; o; o >>= 1) {
        sq += __shfl_xor_sync(0xFFFFFFFFu, sq, o);
        sk += __shfl_xor_sync(0xFFFFFFFFu, sk, o);
    }
    const float nq = fmaxf(sqrtf(sq), 1e-12f);
    if (lane == 0) nks[c] = fmaxf(sqrtf(sk), 1e-12f);

    // G row: fully unrolled so the 24 independent reductions interleave
    float gval = 0.f;
#pragma unroll
    for (int d = 0; d < 24; d++) {
        float s = 0.f;
#pragma unroll
        for (int j = 0; j < 6; j++)
            s = fmaf(t1[j], Wks[d][lane + 32 * j], s);
#pragma unroll
        for (int o = 16; o; o >>= 1) s += __shfl_xor_sync(0xFFFFFFFFu, s, o);
        if (lane == d) gval = s;
    }
    __syncthreads();

    const float tp = temp[h];
    const float nk = (lane < 24) ? nks[lane] : 1.f;
    float l = (lane < 24) ? gval * tp / (nq * nk) : -1e30f;
    float mx = l;
#pragma unroll
    for (int o = 16; o; o >>= 1) mx = fmaxf(mx, __shfl_xor_sync(0xFFFFFFFFu, mx, o));
    const float e = (lane < 24) ? expf(l - mx) : 0.f;
    float ssum = e;
#pragma unroll
    for (int o = 16; o; o >>= 1) ssum += __shfl_xor_sync(0xFFFFFFFFu, ssum, o);
    if (lane < 24)
        g_attn[((b * HEADS + h) * CH + c) * CH + lane] = e / ssum;
}

// =====================================================================
// Kernel 4: FUSED  M = W_out @ blockdiag(attn);  P = M @ W_v  -> fp16.
// grid (6, 6, BATCH), 256 threads.
// =====================================================================
__global__ __launch_bounds__(256) void mp_kernel(const float* __restrict__ wout,
                                                 const float* __restrict__ wqkv) {
    const int b = blockIdx.z;
    const int i0 = blockIdx.y * 32, j0 = blockIdx.x * 32;
    __shared__ float At[HEADS * CH * CH];
    __shared__ float Ms[32][201];
    __shared__ float Ws[32][33];
    const int t = threadIdx.x;

    for (int idx = t; idx < HEADS * CH * CH; idx += 256)
        At[idx] = g_attn[b * HEADS * CH * CH + idx];
    __syncthreads();

    for (int idx = t; idx < 32 * 192; idx += 256) {
        const int mi = idx / 192, k = idx % 192;
        const int h = k / CH, d = k % CH;
        const float* wrow = wout + (i0 + mi) * CCH + h * CH;
        const float* acol = At + h * 576 + d;
        float s = 0.f;
#pragma unroll
        for (int c = 0; c < CH; c++) s = fmaf(wrow[c], acol[c * CH], s);
        Ms[mi][k] = s;
    }
    __syncthreads();

    const int tx = t % 32, ty = t / 32;
    float acc[4] = {0.f, 0.f, 0.f, 0.f};
#pragma unroll 1
    for (int k0 = 0; k0 < CCH; k0 += 32) {
        const int r0 = t / 32, kk = t % 32;
#pragma unroll
        for (int rr = 0; rr < 32; rr += 8)
            Ws[r0 + rr][kk] = wqkv[(2 * CCH + k0 + r0 + rr) * CCH + j0 + kk];
        __syncthreads();
#pragma unroll
        for (int k2 = 0; k2 < 32; k2++) {
            const float bv = Ws[k2][tx];
#pragma unroll
            for (int u = 0; u < 4; u++)
                acc[u] = fmaf(Ms[ty + 8 * u][k0 + k2], bv, acc[u]);
        }
        __syncthreads();
    }
#pragma unroll
    for (int u = 0; u < 4; u++)
        g_Ph[b * CCH * CCH + (i0 + ty + 8 * u) * CCH + j0 + tx] = __float2half(acc[u]);
}

// =====================================================================
// Kernel 5: Y = P @ X via cp.async + ldmatrix. grid (3, 512, BATCH).
// =====================================================================
__global__ __launch_bounds__(256) void y_h2(float* __restrict__ Y) {
    const int b  = blockIdx.z;
    const int i0 = blockIdx.x * 64;
    const int n0 = blockIdx.y * 128;

    __shared__ __align__(16) __half Ps[64][200];
    __shared__ __align__(16) __half Xs[2][32][136];
    const uint32_t sbP = s2u(Ps), sbX = s2u(Xs);

    const int t = threadIdx.x, lane = t & 31, wid = t >> 5;
    const int g = lane >> 2, tg = lane & 3;
    const int lr = lane & 15, lu = lane >> 4;
    const int lb7 = lane & 7, lb8 = (lane >> 3) & 1, lb16 = lane >> 4;
    const int wm = (wid & 1) * 32, wn = (wid >> 1) * 32;

    const __half* Pbh = g_Ph + b * CCH * CCH;
    const __half* Xb = g_Xh + (size_t)b * CCH * NPIX;

#pragma unroll
    for (int i = 0; i < 6; i++) {
        const int idx = t + i * 256;
        const int r = idx / 24, c16 = idx % 24;
        *(uint4*)&Ps[r][c16 * 8] = *(const uint4*)(Pbh + (i0 + r) * CCH + c16 * 8);
    }

    const int xr = t >> 3, xu = (t & 7) * 2;
    const __half* srcX = Xb + (size_t)xr * NPIX + n0 + xu * 8;
    const uint32_t dX = sbX + xr * 272 + xu * 16;
    CPA16(dX, srcX);
    CPA16(dX + 16, srcX + 8);
    CPCOMMIT();

    float acc[2][4][4];
#pragma unroll
    for (int mi = 0; mi < 2; mi++)
#pragma unroll
        for (int nj = 0; nj < 4; nj++)
#pragma unroll
            for (int u = 0; u < 4; u++) acc[mi][nj][u] = 0.f;

    int buf = 0;
#pragma unroll 1
    for (int kt = 0; kt < 6; kt++) {
        if (kt + 1 < 6) {
            const uint32_t bo = (buf ^ 1) * 8704;
            const __half* s2 = srcX + (size_t)(kt + 1) * 32 * NPIX;
            CPA16(dX + bo, s2);
            CPA16(dX + bo + 16, s2 + 8);
            CPCOMMIT();
            CPWAIT(1);
        } else {
            CPWAIT(0);
        }
        __syncthreads();

        const uint32_t bo = buf * 8704;
#pragma unroll
        for (int kk = 0; kk < 32; kk += 16) {
            const int ku = kt * 4 + (kk >> 3);
            unsigned af[2][4], bf[4][2], tmp[4];
#pragma unroll
            for (int mi = 0; mi < 2; mi++)
                ldm_x4(af[mi], sbP + (wm + mi * 16 + lr) * 400 + (ku + lu) * 16);
            {
                const int rowb = kk + lb7 + lb8 * 8;
                const int un = (wn >> 3) + lb16;
                ldm_x4_t(tmp, sbX + bo + rowb * 272 + un * 16);
                bf[0][0] = tmp[0]; bf[0][1] = tmp[1];
                bf[1][0] = tmp[2]; bf[1][1] = tmp[3];
                ldm_x4_t(tmp, sbX + bo + rowb * 272 + (un + 2) * 16);
                bf[2][0] = tmp[0]; bf[2][1] = tmp[1];
                bf[3][0] = tmp[2]; bf[3][1] = tmp[3];
            }
#pragma unroll
            for (int mi = 0; mi < 2; mi++)
#pragma unroll
                for (int nj = 0; nj < 4; nj++)
                    mma_h(acc[mi][nj], af[mi], bf[nj][0], bf[nj][1]);
        }
        __syncthreads();
        buf ^= 1;
    }

    float* Yb = Y + (size_t)b * CCH * NPIX;
#pragma unroll
    for (int mi = 0; mi < 2; mi++)
#pragma unroll
        for (int nj = 0; nj < 4; nj++) {
            const int row = i0 + wm + mi * 16 + g;
            const int col = n0 + wn + nj * 8 + 2 * tg;
            *(float2*)&Yb[(size_t)row * NPIX + col]       = make_float2(acc[mi][nj][0], acc[mi][nj][1]);
            *(float2*)&Yb[(size_t)(row + 8) * NPIX + col] = make_float2(acc[mi][nj][2], acc[mi][nj][3]);
        }
}

// =====================================================================
// Launch
// =====================================================================
extern "C" void kernel_launch(void* const* d_in, const int* in_sizes, int n_in,
                              void* d_out, int out_size) {
    const float* x    = (const float*)d_in[0];
    const float* wqkv = (const float*)d_in[1];
    const float* wout = (const float*)d_in[2];
    const float* temp = (const float*)d_in[3];
    float* y          = (float*)d_out;
    (void)in_sizes; (void)n_in; (void)out_size;

    static bool attr_set = false;
    if (!attr_set) {
        cudaFuncSetAttribute(gram_f, cudaFuncAttributeMaxDynamicSharedMemorySize, GF_SMEM);
        attr_set = true;
    }

    gram_f<<<dim3(GSPLIT, BATCH), 256, GF_SMEM>>>(x);
    gram_reduce6<<<192, 256>>>();
    qk_kernel<<<dim3(12, 3, BATCH), 256>>>(wqkv);
    attn3<<<dim3(HEADS, BATCH), 768>>>(wqkv, temp);
    mp_kernel<<<dim3(6, 6, BATCH), 256>>>(wout, wqkv);
    y_h2<<<dim3(3, 512, BATCH), 256>>>(y);
}